// round 13
// baseline (speedup 1.0000x reference)
#include <cuda_runtime.h>
#include <math.h>

#define BATCH_MAX 65536
#define FEAT 584
#define FEAT_PAD 592

// smem layout: 4 pair-regions x 4032 floats, then table block
#define TBL 16128
#define CONV_SMEM ((16128 + 576) * 4)

typedef unsigned long long u64t;

__device__ float g_feats[(size_t)BATCH_MAX * FEAT_PAD + 16]; // +16 pad for float4 tails

// Weight copies (all tf32 fragment-major)
__device__ unsigned g_w1frag[4 * 2 * 64];   // conv1 W1 (K=27 pad 32, N=16)
__device__ unsigned g_bfrag[74 * 24 * 64];  // fc1 B
__device__ unsigned g_w2frag[16 * 8 * 64];  // heads W2
__device__ unsigned g_w3frag[36 * 8 * 64];  // conv3 W3
__device__ unsigned g_w2cfrag[18 * 4 * 64]; // conv2 W2

__device__ __forceinline__ unsigned f2tf32(float v) {
    unsigned o; asm("cvt.rna.tf32.f32 %0, %1;" : "=r"(o) : "f"(v)); return o;
}
#define MMA_TF32(accp, a0, a1, a2, a3, bx, by)                                \
    asm volatile(                                                             \
        "mma.sync.aligned.m16n8k8.row.col.f32.tf32.tf32.f32 "                 \
        "{%0,%1,%2,%3}, {%4,%5,%6,%7}, {%8,%9}, {%0,%1,%2,%3};"               \
        : "+f"((accp)[0]), "+f"((accp)[1]), "+f"((accp)[2]), "+f"((accp)[3])  \
        : "r"(a0), "r"(a1), "r"(a2), "r"(a3), "r"(bx), "r"(by))

// ---------------------------------------------------------------------------
// Kernel 0: all weight pre-bakes merged (disjoint outputs, idx-guarded).
// ---------------------------------------------------------------------------
__global__ void k_prep(const float* __restrict__ w1,
                       const float* __restrict__ w2,
                       const float* __restrict__ w3,
                       const float* __restrict__ ptw1,
                       const float* __restrict__ cfw1,
                       const float* __restrict__ ptw2)
{
    const int idx = blockIdx.x * 256 + threadIdx.x;

    if (idx < 512) {                       // conv1 W1: K=27 (pad 32), N=16
        const int r = idx & 1;
        const int l = (idx >> 1) & 31;
        const int j = (idx >> 6) & 1;
        const int k8 = idx >> 7;
        const int k = k8 * 8 + r * 4 + (l & 3);
        const int n = j * 8 + (l >> 2);
        g_w1frag[idx] = (k < 27) ? f2tf32(w1[(size_t)n * 27 + k]) : 0u;
    }
    if (idx < 74 * 24 * 64) {              // fc1 B
        const int r = idx & 1;
        const int l = (idx >> 1) & 31;
        const int j = (idx >> 6) % 24;
        const int K8 = idx / (24 * 64);
        const int k = K8 * 8 + r * 4 + (l & 3);
        const int n = j * 8 + (l >> 2);
        float v = 0.f;
        if (k < 584)
            v = (n < 128) ? ptw1[(size_t)k * 128 + n] : cfw1[(size_t)k * 64 + (n - 128)];
        g_bfrag[idx] = f2tf32(v);
    }
    if (idx < 16 * 8 * 64) {               // heads W2
        const int r = idx & 1;
        const int l = (idx >> 1) & 31;
        const int j = (idx >> 6) & 7;
        const int k8 = idx >> 9;
        const int k = k8 * 8 + r * 4 + (l & 3);
        const int n = j * 8 + (l >> 2);
        g_w2frag[idx] = f2tf32(ptw2[(size_t)k * 64 + n]);
    }
    if (idx < 36 * 8 * 64) {               // conv3 W3
        const int r = idx & 1;
        const int l = (idx >> 1) & 31;
        const int j = (idx >> 6) & 7;
        const int k8 = idx >> 9;
        const int k = k8 * 8 + r * 4 + (l & 3);
        const int n = j * 8 + (l >> 2);
        g_w3frag[idx] = f2tf32(w3[(size_t)n * 288 + k]);
    }
    if (idx < 18 * 4 * 64) {               // conv2 W2
        const int r = idx & 1;
        const int l = (idx >> 1) & 31;
        const int j = (idx >> 6) & 3;
        const int k8 = idx >> 8;
        const int k = k8 * 8 + r * 4 + (l & 3);
        const int n = j * 8 + (l >> 2);
        g_w2cfrag[idx] = f2tf32(w2[(size_t)n * 144 + k]);
    }
}

// ---------------------------------------------------------------------------
// conv1 mma tile: rows r = s*36 + (y*6+x), K=32 (27 real), N=16.
// A from padded inp planes (region offset 0); epilogue bias+relu -> h1p.
// ---------------------------------------------------------------------------
__device__ __forceinline__ void conv1_tile(
    float* smf, const int* offk1, const float* b1s,
    int mt, int g, int tg, int lane)
{
    const int r1 = mt * 16 + g, r2 = r1 + 8;
    const int s1 = r1 / 36, p1 = r1 - 36 * s1;
    const int s2 = r2 / 36, p2 = r2 - 36 * s2;
    const int base1 = (s1 >> 1) * 4032 + (s1 & 1) + 2 * ((p1 / 6) * 8 + (p1 % 6));
    const int base2 = (s2 >> 1) * 4032 + (s2 & 1) + 2 * ((p2 / 6) * 8 + (p2 % 6));

    float acc[2][4];
    #pragma unroll
    for (int j = 0; j < 2; j++)
        #pragma unroll
        for (int q = 0; q < 4; q++) acc[j][q] = 0.f;

    #pragma unroll
    for (int k8 = 0; k8 < 4; k8++) {
        const int oa = offk1[k8 * 8 + tg];
        const int oc = offk1[k8 * 8 + tg + 4];
        const unsigned a0 = f2tf32(smf[base1 + oa]);
        const unsigned a1 = f2tf32(smf[base2 + oa]);
        const unsigned a2 = f2tf32(smf[base1 + oc]);
        const unsigned a3 = f2tf32(smf[base2 + oc]);
        #pragma unroll
        for (int j = 0; j < 2; j++) {
            const uint2 b = __ldg((const uint2*)g_w1frag + (k8 * 2 + j) * 32 + lane);
            MMA_TF32(acc[j], a0, a1, a2, a3, b.x, b.y);
        }
    }
    #pragma unroll
    for (int j = 0; j < 2; j++)
        #pragma unroll
        for (int q = 0; q < 4; q++) {
            const int n = j * 8 + tg * 2 + (q & 1);   // co
            const int r = (q < 2) ? r1 : r2;
            const int s = r / 36, p = r - 36 * s;
            const int y = p / 6, x = p - 6 * y;
            smf[(s >> 1) * 4032 + 384 + 2 * (n * 64 + (y + 1) * 8 + (x + 1)) + (s & 1)]
                = fmaxf(acc[j][q] + b1s[n], 0.f);
        }
}

// ---------------------------------------------------------------------------
// conv2 mma tile (fused relu+pool): rows r = s*36 + q*4 + sub
// ---------------------------------------------------------------------------
__device__ __forceinline__ int c2_rowbase(int r)
{
    const int s = r / 36, rem = r - 36 * s;
    const int q = rem >> 2, sub = rem & 3;
    const int qy = q / 3, qx = q - 3 * qy;
    const int py = 2 * qy + (sub >> 1);
    const int px = 2 * qx + (sub & 1);
    return (s >> 1) * 4032 + 384 + (s & 1) + 2 * (py * 8 + px);
}

__device__ __forceinline__ void conv2_tile(
    float* smf, const int* offk2, const float* b2s,
    int mt, int g, int tg, int lane)
{
    const int r1 = mt * 16 + g, r2 = r1 + 8;
    const int base1 = c2_rowbase(r1), base2 = c2_rowbase(r2);

    float acc[4][4];
    #pragma unroll
    for (int j = 0; j < 4; j++)
        #pragma unroll
        for (int q = 0; q < 4; q++) acc[j][q] = 0.f;

    #pragma unroll 3
    for (int k8 = 0; k8 < 18; k8++) {
        const int oa = offk2[k8 * 8 + tg];
        const int oc = offk2[k8 * 8 + tg + 4];
        const unsigned a0 = f2tf32(smf[base1 + oa]);
        const unsigned a1 = f2tf32(smf[base2 + oa]);
        const unsigned a2 = f2tf32(smf[base1 + oc]);
        const unsigned a3 = f2tf32(smf[base2 + oc]);
        #pragma unroll
        for (int j = 0; j < 4; j++) {
            const uint2 b = __ldg((const uint2*)g_w2cfrag + (k8 * 4 + j) * 32 + lane);
            MMA_TF32(acc[j], a0, a1, a2, a3, b.x, b.y);
        }
    }

    #pragma unroll
    for (int j = 0; j < 4; j++)
        #pragma unroll
        for (int q = 0; q < 4; q++) {
            float v = acc[j][q];
            v = fmaxf(v, __shfl_xor_sync(0xffffffffu, v, 4));
            v = fmaxf(v, __shfl_xor_sync(0xffffffffu, v, 8));
            acc[j][q] = v;
        }
    if ((g & 3) == 0) {
        #pragma unroll
        for (int j = 0; j < 4; j++)
            #pragma unroll
            for (int q = 0; q < 4; q++) {
                const int n = j * 8 + tg * 2 + (q & 1);
                const int r = (q < 2) ? r1 : r2;
                const int gq = r >> 2;
                const int s = gq / 9, qp = gq - 9 * s;
                const int py = qp / 3, px = qp - 3 * py;
                smf[(s >> 1) * 4032 + 2432 + (s & 1)
                    + 2 * (n * 25 + (py + 1) * 5 + (px + 1))]
                    = fmaxf(acc[j][q] + b2s[n], 0.f);
            }
    }
}

// ---------------------------------------------------------------------------
// conv3 mma tile
// ---------------------------------------------------------------------------
template<int NN>
__device__ __forceinline__ void conv3_tile(
    float* smf, const int* offk, const float* b3s,
    int mt, int n8lo, int g, int tg, int lane)
{
    const int r1 = mt * 16 + g, r2 = r1 + 8;
    const bool v1 = (r1 < 72), v2 = (r2 < 72);
    int base1 = 0, base2 = 0;
    if (v1) {
        const int s = r1 / 9, p = r1 - 9 * s;
        base1 = (s >> 1) * 4032 + 2432 + (s & 1) + 2 * ((p / 3) * 5 + (p % 3));
    }
    if (v2) {
        const int s = r2 / 9, p = r2 - 9 * s;
        base2 = (s >> 1) * 4032 + 2432 + (s & 1) + 2 * ((p / 3) * 5 + (p % 3));
    }

    float acc[NN][4];
    #pragma unroll
    for (int j = 0; j < NN; j++)
        #pragma unroll
        for (int q = 0; q < 4; q++) acc[j][q] = 0.f;

    #pragma unroll 4
    for (int k8 = 0; k8 < 36; k8++) {
        const int oa = offk[k8 * 8 + tg] * 2;
        const int oc = offk[k8 * 8 + tg + 4] * 2;
        const unsigned a0 = v1 ? f2tf32(smf[base1 + oa]) : 0u;
        const unsigned a1 = v2 ? f2tf32(smf[base2 + oa]) : 0u;
        const unsigned a2 = v1 ? f2tf32(smf[base1 + oc]) : 0u;
        const unsigned a3 = v2 ? f2tf32(smf[base2 + oc]) : 0u;
        #pragma unroll
        for (int j = 0; j < NN; j++) {
            const uint2 b = __ldg((const uint2*)g_w3frag + (k8 * 8 + n8lo + j) * 32 + lane);
            MMA_TF32(acc[j], a0, a1, a2, a3, b.x, b.y);
        }
    }
    #pragma unroll
    for (int j = 0; j < NN; j++)
        #pragma unroll
        for (int q = 0; q < 4; q++) {
            const int n = (n8lo + j) * 8 + tg * 2 + (q & 1);
            const int r = (q < 2) ? r1 : r2;
            if (r < 72)
                smf[(r / 18) * 4032 + 384 + (r % 18) * 65 + n] =
                    fmaxf(acc[j][q] + b3s[n], 0.f);
        }
}

// ---------------------------------------------------------------------------
// Kernel 1: all-tensor-core conv pipeline + quantum sim.
// Tables live in the dedicated TBL smem block (inp regions are conv1's A).
// ---------------------------------------------------------------------------
__global__ __launch_bounds__(128) void k_conv(
    const float* __restrict__ board,
    const float* __restrict__ b1,
    const float* __restrict__ b2,
    const float* __restrict__ b3,
    const float* __restrict__ qp, int nsamp, int s_off)
{
    extern __shared__ float2 smc[];
    float* smf = (float*)smc;
    const int tid = threadIdx.x;
    const int warp = tid >> 5, lane = tid & 31;
    const int pidx = blockIdx.x * 4 + warp;
    const int s0 = s_off + 2 * pidx;
    const bool active = (s0 < nsamp);
    const bool has2 = (s0 + 1 < nsamp);

    float2* inp = smc + (size_t)warp * 2016;

    // table pointers
    int* offk3 = (int*)(smf + TBL);          // 288
    float* b3s = smf + TBL + 288;            // 64
    int* offk2 = (int*)(smf + TBL + 352);    // 144
    float* b2s = smf + TBL + 496;            // 32
    int* offk1 = (int*)(smf + TBL + 528);    // 32
    float* b1s = smf + TBL + 560;            // 16

    // ---- zero per-warp region (covers inp/h1p/pp incl. all padding)
    for (int i = lane; i < 2016; i += 32) inp[i] = make_float2(0.f, 0.f);
    __syncwarp();

    if (active) {
        const float* bs0 = board + (size_t)s0 * 108;
        const float* bs1 = has2 ? bs0 + 108 : bs0;

        for (int i = lane; i < 108; i += 32) {
            int ci = i / 36, r = i - ci * 36;
            int y = r / 6, x = r - y * 6;
            inp[ci * 64 + (y + 1) * 8 + (x + 1)] = make_float2(bs0[i], bs1[i]);
        }

        if (lane < 16) {   // quantum + pad-zero
            const int smp = lane >> 3, qb = lane & 7;
            const int sg = s0 + smp;
            if (sg < nsamp) {
                const float* bq = board + (size_t)sg * 108;
                float xv = bq[qb], xn = bq[(qb + 1) & 7];
                float q = 0.f;
                #pragma unroll
                for (int l = 0; l < 3; l++) {
                    float r0 = __ldg(qp + (l * 8 + qb) * 3 + 0);
                    float r1 = __ldg(qp + (l * 8 + qb) * 3 + 1);
                    float r2 = __ldg(qp + (l * 8 + qb) * 3 + 2);
                    q = sinf(r0 * xv) * cosf(r1 * xn) + tanhf(r2 * q);
                }
                g_feats[(size_t)sg * FEAT_PAD + 576 + qb] = q;
                g_feats[(size_t)sg * FEAT_PAD + 584 + qb] = 0.f;
            }
        }
    }

    // ---- fill tables (disjoint from inp regions; before the block sync)
    for (int i = tid; i < 288; i += 128) {
        const int ci = i / 9, tap = i - ci * 9;
        offk3[i] = ci * 25 + (tap / 3) * 5 + (tap % 3);
    }
    for (int i = tid; i < 144; i += 128) {
        const int ci = i / 9, tap = i - ci * 9;
        offk2[i] = 2 * (ci * 64 + (tap / 3) * 8 + (tap % 3));
    }
    if (tid < 64) b3s[tid] = __ldg(b3 + tid);
    if (tid < 32) {
        b2s[tid] = __ldg(b2 + tid);
        const int k = tid;
        offk1[k] = (k < 27)
            ? 2 * ((k / 9) * 64 + ((k % 9) / 3) * 8 + (k % 9) % 3)
            : 0;   // pad taps read the zeroed inp corner
    }
    if (tid < 16) b1s[tid] = __ldg(b1 + tid);
    __syncthreads();

    {   // conv1 via mma: 18 tiles over 4 warps
        const int g = lane >> 2, tg = lane & 3;
        conv1_tile(smf, offk1, b1s, warp,      g, tg, lane);
        conv1_tile(smf, offk1, b1s, warp + 4,  g, tg, lane);
        conv1_tile(smf, offk1, b1s, warp + 8,  g, tg, lane);
        conv1_tile(smf, offk1, b1s, warp + 12, g, tg, lane);
        if (warp < 2) conv1_tile(smf, offk1, b1s, 16 + warp, g, tg, lane);
    }
    __syncthreads();

    {   // conv2 via mma (+relu+pool): 18 tiles
        const int g = lane >> 2, tg = lane & 3;
        conv2_tile(smf, offk2, b2s, warp,      g, tg, lane);
        conv2_tile(smf, offk2, b2s, warp + 4,  g, tg, lane);
        conv2_tile(smf, offk2, b2s, warp + 8,  g, tg, lane);
        conv2_tile(smf, offk2, b2s, warp + 12, g, tg, lane);
        if (warp < 2) conv2_tile(smf, offk2, b2s, 16 + warp, g, tg, lane);
    }
    __syncthreads();

    {   // conv3 via mma
        const int g = lane >> 2, tg = lane & 3;
        conv3_tile<8>(smf, offk3, b3s, warp, 0, g, tg, lane);
        conv3_tile<2>(smf, offk3, b3s, 4, 2 * warp, g, tg, lane);
    }
    __syncthreads();

    {   // writeback
        const int s = tid >> 4, li = tid & 15;
        const int sg = s_off + blockIdx.x * 8 + s;
        if (sg < nsamp) {
            float* f = g_feats + (size_t)sg * FEAT_PAD;
            for (int i = li; i < 576; i += 16) {
                const int co = i / 9, p = i - 9 * co;
                const int r = s * 9 + p;
                f[i] = smf[(r / 18) * 4032 + 384 + (r % 18) * 65 + co];
            }
        }
    }
}

// ---------------------------------------------------------------------------
// Kernel 2: BM=64, double-buffered tf32 GEMM + tensor-core heads (unchanged).
// ---------------------------------------------------------------------------
#define FC1_SMEM (12992 * 4)

__global__ __launch_bounds__(256) void k_fc1(
    const float* __restrict__ ptb1, const float* __restrict__ cfb1,
    const float* __restrict__ ptb2,
    const float* __restrict__ ptw3, const float* __restrict__ ptb3,
    const float* __restrict__ cfw2, const float* __restrict__ cfb2,
    float* __restrict__ out, int m_off)
{
    extern __shared__ float sfc[];
    unsigned* A_s = (unsigned*)sfc;            // 2 x 1024
    unsigned* B_s = (unsigned*)(sfc + 2048);   // 2 x 3072
    float* C1s    = sfc;                       // 12544 (post-GEMM alias)
    float* BiasS  = sfc + 12544;               // 192
    float* W3s    = sfc + 12736;               // 128
    float* CW2s   = sfc + 12864;               // 64
    float* B2s    = sfc + 12928;               // 64

    const int t = threadIdx.x;
    const int m0 = m_off + blockIdx.x * 64;
    const int warp = t >> 5, lane = t & 31;
    const int wm = warp >> 1, wn = warp & 1;
    const int g = lane >> 2, tg = lane & 3;

    if (t < 192) BiasS[t] = (t < 128) ? __ldg(ptb1 + t) : __ldg(cfb1 + t - 128);
    if (t < 128) W3s[t] = __ldg(ptw3 + t);
    if (t < 64)  { CW2s[t] = __ldg(cfw2 + t); B2s[t] = __ldg(ptb2 + t); }

    float acc[12][4];
    #pragma unroll
    for (int j = 0; j < 12; j++)
        #pragma unroll
        for (int r = 0; r < 4; r++) acc[j][r] = 0.f;

    const bool aload = (t < 128);
    const int am = t >> 1;
    const int kcA = t & 1;
    const int rA = am & 15, mtA = (am >> 4) & 3;
    const int baseA = ((kcA * 4 + mtA) * 32 + (rA & 7) * 4) * 4 + (rA >> 3);
    const float* arow = g_feats + (size_t)(m0 + (am & 63)) * FEAT_PAD + kcA * 8;

    float4 av0 = make_float4(0.f, 0.f, 0.f, 0.f);
    float4 av1 = av0;
    if (aload) { av0 = *(const float4*)(arow); av1 = *(const float4*)(arow + 4); }
    uint4 bv0 = *(const uint4*)(g_bfrag + t * 12);
    uint4 bv1 = *(const uint4*)(g_bfrag + t * 12 + 4);
    uint4 bv2 = *(const uint4*)(g_bfrag + t * 12 + 8);

    int p = 0;
    for (int it = 0; it < 37; ++it) {
        unsigned* Ab = A_s + p * 1024;
        unsigned* Bb = B_s + p * 3072;
        if (aload) {
            Ab[baseA + 0 * 4 + 0] = f2tf32(av0.x);
            Ab[baseA + 1 * 4 + 0] = f2tf32(av0.y);
            Ab[baseA + 2 * 4 + 0] = f2tf32(av0.z);
            Ab[baseA + 3 * 4 + 0] = f2tf32(av0.w);
            Ab[baseA + 0 * 4 + 2] = f2tf32(av1.x);
            Ab[baseA + 1 * 4 + 2] = f2tf32(av1.y);
            Ab[baseA + 2 * 4 + 2] = f2tf32(av1.z);
            Ab[baseA + 3 * 4 + 2] = f2tf32(av1.w);
        }
        *(uint4*)(Bb + t * 12)     = bv0;
        *(uint4*)(Bb + t * 12 + 4) = bv1;
        *(uint4*)(Bb + t * 12 + 8) = bv2;
        __syncthreads();
        if (it < 36) {
            if (aload) {
                av0 = *(const float4*)(arow + (it + 1) * 16);
                av1 = *(const float4*)(arow + (it + 1) * 16 + 4);
            }
            const unsigned* bsrc = g_bfrag + (it + 1) * 3072 + t * 12;
            bv0 = *(const uint4*)(bsrc);
            bv1 = *(const uint4*)(bsrc + 4);
            bv2 = *(const uint4*)(bsrc + 8);
        }
        #pragma unroll
        for (int kc = 0; kc < 2; kc++) {
            const uint4 v = *(const uint4*)(Ab + ((kc * 4 + wm) * 32 + lane) * 4);
            #pragma unroll
            for (int j = 0; j < 12; j++) {
                const uint2 b = *(const uint2*)(Bb + ((kc * 24 + wn * 12 + j) * 32 + lane) * 2);
                MMA_TF32(acc[j], v.x, v.y, v.z, v.w, b.x, b.y);
            }
        }
        p ^= 1;
    }
    __syncthreads();

    #pragma unroll
    for (int j = 0; j < 12; j++)
        #pragma unroll
        for (int r = 0; r < 4; r++) {
            const int m = wm * 16 + ((r >> 1) << 3) + g;
            const int n = wn * 96 + j * 8 + tg * 2 + (r & 1);
            C1s[m * 196 + n] = fmaxf(acc[j][r] + BiasS[n], 0.f);
        }
    __syncthreads();

    if (warp < 4) {
        const int base = warp * 16;
        float hacc[8][4];
        #pragma unroll
        for (int j = 0; j < 8; j++)
            #pragma unroll
            for (int r = 0; r < 4; r++) hacc[j][r] = 0.f;

        #pragma unroll 4
        for (int k8 = 0; k8 < 16; k8++) {
            const float* cA = C1s + base * 196 + k8 * 8;
            const unsigned a0 = f2tf32(cA[g * 196 + tg]);
            const unsigned a1 = f2tf32(cA[(g + 8) * 196 + tg]);
            const unsigned a2 = f2tf32(cA[g * 196 + tg + 4]);
            const unsigned a3 = f2tf32(cA[(g + 8) * 196 + tg + 4]);
            #pragma unroll
            for (int j = 0; j < 8; j++) {
                const uint2 b = __ldg((const uint2*)g_w2frag + (k8 * 8 + j) * 32 + lane);
                MMA_TF32(hacc[j], a0, a1, a2, a3, b.x, b.y);
            }
        }

        float l0g = 0.f, l1g = 0.f, l0h = 0.f, l1h = 0.f;
        #pragma unroll
        for (int j = 0; j < 8; j++)
            #pragma unroll
            for (int r = 0; r < 4; r++) {
                const int n = j * 8 + tg * 2 + (r & 1);
                const float v = fmaxf(hacc[j][r] + B2s[n], 0.f);
                const float w30 = W3s[n * 2], w31 = W3s[n * 2 + 1];
                if (r < 2) { l0g = fmaf(v, w30, l0g); l1g = fmaf(v, w31, l1g); }
                else       { l0h = fmaf(v, w30, l0h); l1h = fmaf(v, w31, l1h); }
            }
        #pragma unroll
        for (int off = 1; off <= 2; off <<= 1) {
            l0g += __shfl_xor_sync(0xffffffffu, l0g, off);
            l1g += __shfl_xor_sync(0xffffffffu, l1g, off);
            l0h += __shfl_xor_sync(0xffffffffu, l0h, off);
            l1h += __shfl_xor_sync(0xffffffffu, l1h, off);
        }
        if (tg == 0) {
            const float b30 = __ldg(ptb3 + 0), b31 = __ldg(ptb3 + 1);
            {
                const float l0 = l0g + b30, l1 = l1g + b31;
                const float mx = fmaxf(l0, l1);
                const float e0 = expf(l0 - mx), e1 = expf(l1 - mx);
                const float inv = 1.f / (e0 + e1);
                out[(size_t)(m0 + base + g) * 3 + 0] = e0 * inv;
                out[(size_t)(m0 + base + g) * 3 + 1] = e1 * inv;
            }
            {
                const float l0 = l0h + b30, l1 = l1h + b31;
                const float mx = fmaxf(l0, l1);
                const float e0 = expf(l0 - mx), e1 = expf(l1 - mx);
                const float inv = 1.f / (e0 + e1);
                out[(size_t)(m0 + base + g + 8) * 3 + 0] = e0 * inv;
                out[(size_t)(m0 + base + g + 8) * 3 + 1] = e1 * inv;
            }
        }
    } else {
        const int base = (warp - 4) * 16;
        for (int i = 0; i < 16; i++) {
            const int ml = base + i;
            const float* c1 = C1s + ml * 196;
            float cc = c1[128 + lane] * CW2s[lane] + c1[160 + lane] * CW2s[lane + 32];
            #pragma unroll
            for (int off = 16; off; off >>= 1)
                cc += __shfl_xor_sync(0xffffffffu, cc, off);
            if (lane == 0)
                out[(size_t)(m0 + ml) * 3 + 2] =
                    1.f / (1.f + expf(-(cc + __ldg(cfb2))));
        }
    }
}

// ---------------------------------------------------------------------------
// Launch: 4-chunk conv->fc1 pipeline on two streams (fork/join via events).
// ---------------------------------------------------------------------------
extern "C" void kernel_launch(void* const* d_in, const int* in_sizes, int n_in,
                              void* d_out, int out_size)
{
    const float* board = (const float*)d_in[0];
    // d_in[1] = target_positions (int64) — mathematically unused
    const float* c1w = (const float*)d_in[2];  const float* c1b = (const float*)d_in[3];
    const float* c2w = (const float*)d_in[4];  const float* c2b = (const float*)d_in[5];
    const float* c3w = (const float*)d_in[6];  const float* c3b = (const float*)d_in[7];
    const float* qp  = (const float*)d_in[8];
    const float* ptw1 = (const float*)d_in[9];  const float* ptb1 = (const float*)d_in[10];
    const float* ptw2 = (const float*)d_in[11]; const float* ptb2 = (const float*)d_in[12];
    const float* ptw3 = (const float*)d_in[13]; const float* ptb3 = (const float*)d_in[14];
    const float* cfw1 = (const float*)d_in[15]; const float* cfb1 = (const float*)d_in[16];
    const float* cfw2 = (const float*)d_in[17]; const float* cfb2 = (const float*)d_in[18];

    int B = in_sizes[0] / 108;
    if (B > BATCH_MAX) B = BATCH_MAX;

    static bool init_done = false;
    static cudaStream_t s2;
    static cudaEvent_t evc[4], evj;
    if (!init_done) {
        cudaFuncSetAttribute(k_conv, cudaFuncAttributeMaxDynamicSharedMemorySize, CONV_SMEM);
        cudaFuncSetAttribute(k_fc1, cudaFuncAttributeMaxDynamicSharedMemorySize, FC1_SMEM);
        cudaStreamCreateWithFlags(&s2, cudaStreamNonBlocking);
        for (int i = 0; i < 4; i++)
            cudaEventCreateWithFlags(&evc[i], cudaEventDisableTiming);
        cudaEventCreateWithFlags(&evj, cudaEventDisableTiming);
        init_done = true;
    }

    const int nch = (B % (512 * 4) == 0) ? 4 : 1;
    const int chunk = B / nch;

    k_prep<<<(74 * 24 * 64 + 255) / 256, 256>>>(c1w, c2w, c3w, ptw1, cfw1, ptw2);

    for (int i = 0; i < nch; i++) {
        k_conv<<<(chunk + 7) / 8, 128, CONV_SMEM>>>(
            board, c1b, c2b, c3b, qp, B, i * chunk);
        cudaEventRecord(evc[i], 0);
    }
    for (int i = 0; i < nch; i++) {
        cudaStreamWaitEvent(s2, evc[i], 0);
        k_fc1<<<chunk / 64, 256, FC1_SMEM, s2>>>(
            ptb1, cfb1, ptb2, ptw3, ptb3, cfw2, cfb2,
            (float*)d_out, i * chunk);
    }
    cudaEventRecord(evj, s2);
    cudaStreamWaitEvent(0, evj, 0);
}

// round 14
// speedup vs baseline: 1.0788x; 1.0788x over previous
#include <cuda_runtime.h>
#include <math.h>

#define BATCH_MAX 65536
#define FEAT 584
#define FEAT_PAD 592

typedef unsigned long long u64t;

__device__ float g_feats[(size_t)BATCH_MAX * FEAT_PAD + 16]; // +16 pad for float4 tails

// Weight copies
__device__ float g_w1t[27 * 16];            // [tap][co]
__device__ unsigned g_bfrag[74 * 24 * 64];  // fc1 B, tf32 fragment-major
__device__ unsigned g_w2frag[16 * 8 * 64];  // heads W2, tf32 fragment-major
__device__ unsigned g_w3frag[36 * 8 * 64];  // conv3 W3, tf32 fragment-major
__device__ unsigned g_w2cfrag[18 * 4 * 64]; // conv2 W2, tf32 fragment-major

// ---- packed f32x2 helpers -------------------------------------------------
__device__ __forceinline__ float2 ffma2(float2 a, float2 b, float2 c) {
    u64t ua = *(u64t*)&a, ub = *(u64t*)&b, uc = *(u64t*)&c, ud;
    asm("fma.rn.f32x2 %0, %1, %2, %3;" : "=l"(ud) : "l"(ua), "l"(ub), "l"(uc));
    return *(float2*)&ud;
}
__device__ __forceinline__ float2 bcast2(float w) { return make_float2(w, w); }
__device__ __forceinline__ float2 fmax2(float2 a, float2 b) {
    return make_float2(fmaxf(a.x, b.x), fmaxf(a.y, b.y));
}
__device__ __forceinline__ unsigned f2tf32(float v) {
    unsigned o; asm("cvt.rna.tf32.f32 %0, %1;" : "=r"(o) : "f"(v)); return o;
}
#define MMA_TF32(accp, a0, a1, a2, a3, bx, by)                                \
    asm volatile(                                                             \
        "mma.sync.aligned.m16n8k8.row.col.f32.tf32.tf32.f32 "                 \
        "{%0,%1,%2,%3}, {%4,%5,%6,%7}, {%8,%9}, {%0,%1,%2,%3};"               \
        : "+f"((accp)[0]), "+f"((accp)[1]), "+f"((accp)[2]), "+f"((accp)[3])  \
        : "r"(a0), "r"(a1), "r"(a2), "r"(a3), "r"(bx), "r"(by))

// ---------------------------------------------------------------------------
// Kernel 0: all weight pre-bakes merged (disjoint outputs, idx-guarded).
// ---------------------------------------------------------------------------
__global__ void k_prep(const float* __restrict__ w1,
                       const float* __restrict__ w2,
                       const float* __restrict__ w3,
                       const float* __restrict__ ptw1,
                       const float* __restrict__ cfw1,
                       const float* __restrict__ ptw2)
{
    const int idx = blockIdx.x * 256 + threadIdx.x;

    if (idx < 432) {                       // conv1 transpose
        int co = idx / 27, r = idx - co * 27;
        g_w1t[r * 16 + co] = w1[idx];
    }
    if (idx < 74 * 24 * 64) {              // fc1 B
        const int r = idx & 1;
        const int l = (idx >> 1) & 31;
        const int j = (idx >> 6) % 24;
        const int K8 = idx / (24 * 64);
        const int k = K8 * 8 + r * 4 + (l & 3);
        const int n = j * 8 + (l >> 2);
        float v = 0.f;
        if (k < 584)
            v = (n < 128) ? ptw1[(size_t)k * 128 + n] : cfw1[(size_t)k * 64 + (n - 128)];
        g_bfrag[idx] = f2tf32(v);
    }
    if (idx < 16 * 8 * 64) {               // heads W2
        const int r = idx & 1;
        const int l = (idx >> 1) & 31;
        const int j = (idx >> 6) & 7;
        const int k8 = idx >> 9;
        const int k = k8 * 8 + r * 4 + (l & 3);
        const int n = j * 8 + (l >> 2);
        g_w2frag[idx] = f2tf32(ptw2[(size_t)k * 64 + n]);
    }
    if (idx < 36 * 8 * 64) {               // conv3 W3
        const int r = idx & 1;
        const int l = (idx >> 1) & 31;
        const int j = (idx >> 6) & 7;
        const int k8 = idx >> 9;
        const int k = k8 * 8 + r * 4 + (l & 3);
        const int n = j * 8 + (l >> 2);
        g_w3frag[idx] = f2tf32(w3[(size_t)n * 288 + k]);
    }
    if (idx < 18 * 4 * 64) {               // conv2 W2
        const int r = idx & 1;
        const int l = (idx >> 1) & 31;
        const int j = (idx >> 6) & 3;
        const int k8 = idx >> 8;
        const int k = k8 * 8 + r * 4 + (l & 3);
        const int n = j * 8 + (l >> 2);
        g_w2cfrag[idx] = f2tf32(w2[(size_t)n * 144 + k]);
    }
}

// ---------------------------------------------------------------------------
// conv2 row mapping: r = s*36 + q*4 + sub
// ---------------------------------------------------------------------------
__device__ __forceinline__ int c2_rowbase(int r)
{
    const int s = r / 36, rem = r - 36 * s;
    const int q = rem >> 2, sub = rem & 3;
    const int qy = q / 3, qx = q - 3 * qy;
    const int py = 2 * qy + (sub >> 1);
    const int px = 2 * qx + (sub & 1);
    return (s >> 1) * 4032 + 384 + (s & 1) + 2 * (py * 8 + px);
}

// ---------------------------------------------------------------------------
// conv2 mma tile (fused relu+pool)
// ---------------------------------------------------------------------------
__device__ __forceinline__ void conv2_tile(
    float* smf, const int* offk2, const float* b2s,
    int mt, int g, int tg, int lane)
{
    const int r1 = mt * 16 + g, r2 = r1 + 8;
    const int base1 = c2_rowbase(r1), base2 = c2_rowbase(r2);

    float acc[4][4];
    #pragma unroll
    for (int j = 0; j < 4; j++)
        #pragma unroll
        for (int q = 0; q < 4; q++) acc[j][q] = 0.f;

    #pragma unroll 3
    for (int k8 = 0; k8 < 18; k8++) {
        const int oa = offk2[k8 * 8 + tg];
        const int oc = offk2[k8 * 8 + tg + 4];
        const unsigned a0 = f2tf32(smf[base1 + oa]);
        const unsigned a1 = f2tf32(smf[base2 + oa]);
        const unsigned a2 = f2tf32(smf[base1 + oc]);
        const unsigned a3 = f2tf32(smf[base2 + oc]);
        #pragma unroll
        for (int j = 0; j < 4; j++) {
            const uint2 b = __ldg((const uint2*)g_w2cfrag + (k8 * 4 + j) * 32 + lane);
            MMA_TF32(acc[j], a0, a1, a2, a3, b.x, b.y);
        }
    }

    #pragma unroll
    for (int j = 0; j < 4; j++)
        #pragma unroll
        for (int q = 0; q < 4; q++) {
            float v = acc[j][q];
            v = fmaxf(v, __shfl_xor_sync(0xffffffffu, v, 4));
            v = fmaxf(v, __shfl_xor_sync(0xffffffffu, v, 8));
            acc[j][q] = v;
        }
    if ((g & 3) == 0) {
        #pragma unroll
        for (int j = 0; j < 4; j++)
            #pragma unroll
            for (int q = 0; q < 4; q++) {
                const int n = j * 8 + tg * 2 + (q & 1);
                const int r = (q < 2) ? r1 : r2;
                const int gq = r >> 2;
                const int s = gq / 9, qp = gq - 9 * s;
                const int py = qp / 3, px = qp - 3 * py;
                smf[(s >> 1) * 4032 + 2432 + (s & 1)
                    + 2 * (n * 25 + (py + 1) * 5 + (px + 1))]
                    = fmaxf(acc[j][q] + b2s[n], 0.f);
            }
    }
}

// ---------------------------------------------------------------------------
// conv3 mma tile
// ---------------------------------------------------------------------------
template<int NN>
__device__ __forceinline__ void conv3_tile(
    float* smf, const int* offk, const float* b3s,
    int mt, int n8lo, int g, int tg, int lane)
{
    const int r1 = mt * 16 + g, r2 = r1 + 8;
    const bool v1 = (r1 < 72), v2 = (r2 < 72);
    int base1 = 0, base2 = 0;
    if (v1) {
        const int s = r1 / 9, p = r1 - 9 * s;
        base1 = (s >> 1) * 4032 + 2432 + (s & 1) + 2 * ((p / 3) * 5 + (p % 3));
    }
    if (v2) {
        const int s = r2 / 9, p = r2 - 9 * s;
        base2 = (s >> 1) * 4032 + 2432 + (s & 1) + 2 * ((p / 3) * 5 + (p % 3));
    }

    float acc[NN][4];
    #pragma unroll
    for (int j = 0; j < NN; j++)
        #pragma unroll
        for (int q = 0; q < 4; q++) acc[j][q] = 0.f;

    #pragma unroll 4
    for (int k8 = 0; k8 < 36; k8++) {
        const int oa = offk[k8 * 8 + tg] * 2;
        const int oc = offk[k8 * 8 + tg + 4] * 2;
        const unsigned a0 = v1 ? f2tf32(smf[base1 + oa]) : 0u;
        const unsigned a1 = v2 ? f2tf32(smf[base2 + oa]) : 0u;
        const unsigned a2 = v1 ? f2tf32(smf[base1 + oc]) : 0u;
        const unsigned a3 = v2 ? f2tf32(smf[base2 + oc]) : 0u;
        #pragma unroll
        for (int j = 0; j < NN; j++) {
            const uint2 b = __ldg((const uint2*)g_w3frag + (k8 * 8 + n8lo + j) * 32 + lane);
            MMA_TF32(acc[j], a0, a1, a2, a3, b.x, b.y);
        }
    }
    #pragma unroll
    for (int j = 0; j < NN; j++)
        #pragma unroll
        for (int q = 0; q < 4; q++) {
            const int n = (n8lo + j) * 8 + tg * 2 + (q & 1);
            const int r = (q < 2) ? r1 : r2;
            if (r < 72)
                smf[(r / 18) * 4032 + 384 + (r % 18) * 65 + n] =
                    fmaxf(acc[j][q] + b3s[n], 0.f);
        }
}

// ---------------------------------------------------------------------------
// Kernel 1: conv pipeline + quantum sim (round-12 structure; conv1 now uses
// a sliding 3-row register window: 120 LDS.64/thread instead of 486).
// ---------------------------------------------------------------------------
__global__ __launch_bounds__(128) void k_conv(
    const float* __restrict__ board,
    const float* __restrict__ b1,
    const float* __restrict__ b2,
    const float* __restrict__ b3,
    const float* __restrict__ qp, int nsamp, int s_off)
{
    extern __shared__ float2 smc[];
    float* smf = (float*)smc;
    const int tid = threadIdx.x;
    const int warp = tid >> 5, lane = tid & 31;
    const int pidx = blockIdx.x * 4 + warp;
    const int s0 = s_off + 2 * pidx;
    const bool active = (s0 < nsamp);
    const bool has2 = (s0 + 1 < nsamp);

    float2* inp = smc + (size_t)warp * 2016;
    float2* h1p = inp + 192;

    for (int i = lane; i < 2016; i += 32) inp[i] = make_float2(0.f, 0.f);
    __syncwarp();

    if (active) {
        const float* bs0 = board + (size_t)s0 * 108;
        const float* bs1 = has2 ? bs0 + 108 : bs0;

        for (int i = lane; i < 108; i += 32) {
            int ci = i / 36, r = i - ci * 36;
            int y = r / 6, x = r - y * 6;
            inp[ci * 64 + (y + 1) * 8 + (x + 1)] = make_float2(bs0[i], bs1[i]);
        }

        if (lane < 16) {
            const int smp = lane >> 3, qb = lane & 7;
            const int sg = s0 + smp;
            if (sg < nsamp) {
                const float* bq = board + (size_t)sg * 108;
                float xv = bq[qb], xn = bq[(qb + 1) & 7];
                float q = 0.f;
                #pragma unroll
                for (int l = 0; l < 3; l++) {
                    float r0 = __ldg(qp + (l * 8 + qb) * 3 + 0);
                    float r1 = __ldg(qp + (l * 8 + qb) * 3 + 1);
                    float r2 = __ldg(qp + (l * 8 + qb) * 3 + 2);
                    q = sinf(r0 * xv) * cosf(r1 * xn) + tanhf(r2 * q);
                }
                g_feats[(size_t)sg * FEAT_PAD + 576 + qb] = q;
                g_feats[(size_t)sg * FEAT_PAD + 584 + qb] = 0.f;
            }
        }
        __syncwarp();

        {   // conv1: sliding 3-row window. co = lane&15, half = lane>>4
            // (output rows half*3 .. half*3+2). Rows loaded once.
            const int co = lane & 15, half = lane >> 4;
            const float2 zero = make_float2(0.f, 0.f);
            float2 acc[3][6];
            {
                const float2 bias = bcast2(__ldg(b1 + co));
                #pragma unroll
                for (int y = 0; y < 3; y++)
                    #pragma unroll
                    for (int x = 0; x < 6; x++) acc[y][x] = bias;
            }
            #pragma unroll
            for (int ci = 0; ci < 3; ci++) {
                float2 w[9];
                #pragma unroll
                for (int i = 0; i < 9; i++)
                    w[i] = bcast2(__ldg(g_w1t + (ci * 9 + i) * 16 + co));
                const float2* cp = inp + ci * 64 + half * 3 * 8; // padded row half*3
                float2 r[3][8];
                #pragma unroll
                for (int j = 0; j < 8; j++) { r[0][j] = cp[j]; r[1][j] = cp[8 + j]; }
                #pragma unroll
                for (int y = 0; y < 3; y++) {
                    #pragma unroll
                    for (int j = 0; j < 8; j++) r[(y + 2) % 3][j] = cp[(y + 2) * 8 + j];
                    #pragma unroll
                    for (int x = 0; x < 6; x++) {
                        float2 a = acc[y][x];
                        a = ffma2(r[(y + 0) % 3][x + 0], w[0], a);
                        a = ffma2(r[(y + 0) % 3][x + 1], w[1], a);
                        a = ffma2(r[(y + 0) % 3][x + 2], w[2], a);
                        a = ffma2(r[(y + 1) % 3][x + 0], w[3], a);
                        a = ffma2(r[(y + 1) % 3][x + 1], w[4], a);
                        a = ffma2(r[(y + 1) % 3][x + 2], w[5], a);
                        a = ffma2(r[(y + 2) % 3][x + 0], w[6], a);
                        a = ffma2(r[(y + 2) % 3][x + 1], w[7], a);
                        a = ffma2(r[(y + 2) % 3][x + 2], w[8], a);
                        acc[y][x] = a;
                    }
                }
            }
            #pragma unroll
            for (int y = 0; y < 3; y++)
                #pragma unroll
                for (int x = 0; x < 6; x++) {
                    const int yy = half * 3 + y;
                    h1p[co * 64 + (yy + 1) * 8 + x + 1] = fmax2(acc[y][x], zero);
                }
        }
    }
    __syncthreads();

    for (int i = tid; i < 288; i += 128) {
        const int ci = i / 9, tap = i - ci * 9;
        ((int*)smf)[i] = ci * 25 + (tap / 3) * 5 + (tap % 3);
    }
    for (int i = tid; i < 144; i += 128) {
        const int ci = i / 9, tap = i - ci * 9;
        ((int*)(smf + 4032))[i] = 2 * (ci * 64 + (tap / 3) * 8 + (tap % 3));
    }
    if (tid < 64) smf[288 + tid] = __ldg(b3 + tid);
    if (tid < 32) smf[4200 + tid] = __ldg(b2 + tid);
    __syncthreads();

    {   // conv2 via mma
        const int g = lane >> 2, tg = lane & 3;
        const int* offk2 = (const int*)(smf + 4032);
        const float* b2s = smf + 4200;
        conv2_tile(smf, offk2, b2s, warp,      g, tg, lane);
        conv2_tile(smf, offk2, b2s, warp + 4,  g, tg, lane);
        conv2_tile(smf, offk2, b2s, warp + 8,  g, tg, lane);
        conv2_tile(smf, offk2, b2s, warp + 12, g, tg, lane);
        if (warp < 2) conv2_tile(smf, offk2, b2s, 16 + warp, g, tg, lane);
    }
    __syncthreads();

    {   // conv3 via mma
        const int g = lane >> 2, tg = lane & 3;
        const int* offk = (const int*)smf;
        const float* b3s = smf + 288;
        conv3_tile<8>(smf, offk, b3s, warp, 0, g, tg, lane);
        conv3_tile<2>(smf, offk, b3s, 4, 2 * warp, g, tg, lane);
    }
    __syncthreads();

    {   // writeback
        const int s = tid >> 4, li = tid & 15;
        const int sg = s_off + blockIdx.x * 8 + s;
        if (sg < nsamp) {
            float* f = g_feats + (size_t)sg * FEAT_PAD;
            for (int i = li; i < 576; i += 16) {
                const int co = i / 9, p = i - 9 * co;
                const int r = s * 9 + p;
                f[i] = smf[(r / 18) * 4032 + 384 + (r % 18) * 65 + co];
            }
        }
    }
}

// ---------------------------------------------------------------------------
// Kernel 2: BM=64, double-buffered tf32 GEMM + tensor-core heads (round-12).
// ---------------------------------------------------------------------------
#define FC1_SMEM (12992 * 4)

__global__ __launch_bounds__(256) void k_fc1(
    const float* __restrict__ ptb1, const float* __restrict__ cfb1,
    const float* __restrict__ ptb2,
    const float* __restrict__ ptw3, const float* __restrict__ ptb3,
    const float* __restrict__ cfw2, const float* __restrict__ cfb2,
    float* __restrict__ out, int m_off)
{
    extern __shared__ float sfc[];
    unsigned* A_s = (unsigned*)sfc;            // 2 x 1024
    unsigned* B_s = (unsigned*)(sfc + 2048);   // 2 x 3072
    float* C1s    = sfc;                       // 12544 (post-GEMM alias)
    float* BiasS  = sfc + 12544;               // 192
    float* W3s    = sfc + 12736;               // 128
    float* CW2s   = sfc + 12864;               // 64
    float* B2s    = sfc + 12928;               // 64

    const int t = threadIdx.x;
    const int m0 = m_off + blockIdx.x * 64;
    const int warp = t >> 5, lane = t & 31;
    const int wm = warp >> 1, wn = warp & 1;
    const int g = lane >> 2, tg = lane & 3;

    if (t < 192) BiasS[t] = (t < 128) ? __ldg(ptb1 + t) : __ldg(cfb1 + t - 128);
    if (t < 128) W3s[t] = __ldg(ptw3 + t);
    if (t < 64)  { CW2s[t] = __ldg(cfw2 + t); B2s[t] = __ldg(ptb2 + t); }

    float acc[12][4];
    #pragma unroll
    for (int j = 0; j < 12; j++)
        #pragma unroll
        for (int r = 0; r < 4; r++) acc[j][r] = 0.f;

    const bool aload = (t < 128);
    const int am = t >> 1;
    const int kcA = t & 1;
    const int rA = am & 15, mtA = (am >> 4) & 3;
    const int baseA = ((kcA * 4 + mtA) * 32 + (rA & 7) * 4) * 4 + (rA >> 3);
    const float* arow = g_feats + (size_t)(m0 + (am & 63)) * FEAT_PAD + kcA * 8;

    float4 av0 = make_float4(0.f, 0.f, 0.f, 0.f);
    float4 av1 = av0;
    if (aload) { av0 = *(const float4*)(arow); av1 = *(const float4*)(arow + 4); }
    uint4 bv0 = *(const uint4*)(g_bfrag + t * 12);
    uint4 bv1 = *(const uint4*)(g_bfrag + t * 12 + 4);
    uint4 bv2 = *(const uint4*)(g_bfrag + t * 12 + 8);

    int p = 0;
    for (int it = 0; it < 37; ++it) {
        unsigned* Ab = A_s + p * 1024;
        unsigned* Bb = B_s + p * 3072;
        if (aload) {
            Ab[baseA + 0 * 4 + 0] = f2tf32(av0.x);
            Ab[baseA + 1 * 4 + 0] = f2tf32(av0.y);
            Ab[baseA + 2 * 4 + 0] = f2tf32(av0.z);
            Ab[baseA + 3 * 4 + 0] = f2tf32(av0.w);
            Ab[baseA + 0 * 4 + 2] = f2tf32(av1.x);
            Ab[baseA + 1 * 4 + 2] = f2tf32(av1.y);
            Ab[baseA + 2 * 4 + 2] = f2tf32(av1.z);
            Ab[baseA + 3 * 4 + 2] = f2tf32(av1.w);
        }
        *(uint4*)(Bb + t * 12)     = bv0;
        *(uint4*)(Bb + t * 12 + 4) = bv1;
        *(uint4*)(Bb + t * 12 + 8) = bv2;
        __syncthreads();
        if (it < 36) {
            if (aload) {
                av0 = *(const float4*)(arow + (it + 1) * 16);
                av1 = *(const float4*)(arow + (it + 1) * 16 + 4);
            }
            const unsigned* bsrc = g_bfrag + (it + 1) * 3072 + t * 12;
            bv0 = *(const uint4*)(bsrc);
            bv1 = *(const uint4*)(bsrc + 4);
            bv2 = *(const uint4*)(bsrc + 8);
        }
        #pragma unroll
        for (int kc = 0; kc < 2; kc++) {
            const uint4 v = *(const uint4*)(Ab + ((kc * 4 + wm) * 32 + lane) * 4);
            #pragma unroll
            for (int j = 0; j < 12; j++) {
                const uint2 b = *(const uint2*)(Bb + ((kc * 24 + wn * 12 + j) * 32 + lane) * 2);
                MMA_TF32(acc[j], v.x, v.y, v.z, v.w, b.x, b.y);
            }
        }
        p ^= 1;
    }
    __syncthreads();

    #pragma unroll
    for (int j = 0; j < 12; j++)
        #pragma unroll
        for (int r = 0; r < 4; r++) {
            const int m = wm * 16 + ((r >> 1) << 3) + g;
            const int n = wn * 96 + j * 8 + tg * 2 + (r & 1);
            C1s[m * 196 + n] = fmaxf(acc[j][r] + BiasS[n], 0.f);
        }
    __syncthreads();

    if (warp < 4) {
        const int base = warp * 16;
        float hacc[8][4];
        #pragma unroll
        for (int j = 0; j < 8; j++)
            #pragma unroll
            for (int r = 0; r < 4; r++) hacc[j][r] = 0.f;

        #pragma unroll 4
        for (int k8 = 0; k8 < 16; k8++) {
            const float* cA = C1s + base * 196 + k8 * 8;
            const unsigned a0 = f2tf32(cA[g * 196 + tg]);
            const unsigned a1 = f2tf32(cA[(g + 8) * 196 + tg]);
            const unsigned a2 = f2tf32(cA[g * 196 + tg + 4]);
            const unsigned a3 = f2tf32(cA[(g + 8) * 196 + tg + 4]);
            #pragma unroll
            for (int j = 0; j < 8; j++) {
                const uint2 b = __ldg((const uint2*)g_w2frag + (k8 * 8 + j) * 32 + lane);
                MMA_TF32(hacc[j], a0, a1, a2, a3, b.x, b.y);
            }
        }

        float l0g = 0.f, l1g = 0.f, l0h = 0.f, l1h = 0.f;
        #pragma unroll
        for (int j = 0; j < 8; j++)
            #pragma unroll
            for (int r = 0; r < 4; r++) {
                const int n = j * 8 + tg * 2 + (r & 1);
                const float v = fmaxf(hacc[j][r] + B2s[n], 0.f);
                const float w30 = W3s[n * 2], w31 = W3s[n * 2 + 1];
                if (r < 2) { l0g = fmaf(v, w30, l0g); l1g = fmaf(v, w31, l1g); }
                else       { l0h = fmaf(v, w30, l0h); l1h = fmaf(v, w31, l1h); }
            }
        #pragma unroll
        for (int off = 1; off <= 2; off <<= 1) {
            l0g += __shfl_xor_sync(0xffffffffu, l0g, off);
            l1g += __shfl_xor_sync(0xffffffffu, l1g, off);
            l0h += __shfl_xor_sync(0xffffffffu, l0h, off);
            l1h += __shfl_xor_sync(0xffffffffu, l1h, off);
        }
        if (tg == 0) {
            const float b30 = __ldg(ptb3 + 0), b31 = __ldg(ptb3 + 1);
            {
                const float l0 = l0g + b30, l1 = l1g + b31;
                const float mx = fmaxf(l0, l1);
                const float e0 = expf(l0 - mx), e1 = expf(l1 - mx);
                const float inv = 1.f / (e0 + e1);
                out[(size_t)(m0 + base + g) * 3 + 0] = e0 * inv;
                out[(size_t)(m0 + base + g) * 3 + 1] = e1 * inv;
            }
            {
                const float l0 = l0h + b30, l1 = l1h + b31;
                const float mx = fmaxf(l0, l1);
                const float e0 = expf(l0 - mx), e1 = expf(l1 - mx);
                const float inv = 1.f / (e0 + e1);
                out[(size_t)(m0 + base + g + 8) * 3 + 0] = e0 * inv;
                out[(size_t)(m0 + base + g + 8) * 3 + 1] = e1 * inv;
            }
        }
    } else {
        const int base = (warp - 4) * 16;
        for (int i = 0; i < 16; i++) {
            const int ml = base + i;
            const float* c1 = C1s + ml * 196;
            float cc = c1[128 + lane] * CW2s[lane] + c1[160 + lane] * CW2s[lane + 32];
            #pragma unroll
            for (int off = 16; off; off >>= 1)
                cc += __shfl_xor_sync(0xffffffffu, cc, off);
            if (lane == 0)
                out[(size_t)(m0 + ml) * 3 + 2] =
                    1.f / (1.f + expf(-(cc + __ldg(cfb2))));
        }
    }
}

// ---------------------------------------------------------------------------
// Launch: 4-chunk conv->fc1 pipeline on two streams (fork/join via events).
// ---------------------------------------------------------------------------
extern "C" void kernel_launch(void* const* d_in, const int* in_sizes, int n_in,
                              void* d_out, int out_size)
{
    const float* board = (const float*)d_in[0];
    // d_in[1] = target_positions (int64) — mathematically unused
    const float* c1w = (const float*)d_in[2];  const float* c1b = (const float*)d_in[3];
    const float* c2w = (const float*)d_in[4];  const float* c2b = (const float*)d_in[5];
    const float* c3w = (const float*)d_in[6];  const float* c3b = (const float*)d_in[7];
    const float* qp  = (const float*)d_in[8];
    const float* ptw1 = (const float*)d_in[9];  const float* ptb1 = (const float*)d_in[10];
    const float* ptw2 = (const float*)d_in[11]; const float* ptb2 = (const float*)d_in[12];
    const float* ptw3 = (const float*)d_in[13]; const float* ptb3 = (const float*)d_in[14];
    const float* cfw1 = (const float*)d_in[15]; const float* cfb1 = (const float*)d_in[16];
    const float* cfw2 = (const float*)d_in[17]; const float* cfb2 = (const float*)d_in[18];

    int B = in_sizes[0] / 108;
    if (B > BATCH_MAX) B = BATCH_MAX;

    static bool init_done = false;
    static cudaStream_t s2;
    static cudaEvent_t evc[4], evj;
    if (!init_done) {
        cudaFuncSetAttribute(k_conv, cudaFuncAttributeMaxDynamicSharedMemorySize, 4 * 2016 * 8);
        cudaFuncSetAttribute(k_fc1, cudaFuncAttributeMaxDynamicSharedMemorySize, FC1_SMEM);
        cudaStreamCreateWithFlags(&s2, cudaStreamNonBlocking);
        for (int i = 0; i < 4; i++)
            cudaEventCreateWithFlags(&evc[i], cudaEventDisableTiming);
        cudaEventCreateWithFlags(&evj, cudaEventDisableTiming);
        init_done = true;
    }

    const int nch = (B % (512 * 4) == 0) ? 4 : 1;
    const int chunk = B / nch;

    k_prep<<<(74 * 24 * 64 + 255) / 256, 256>>>(c1w, c2w, c3w, ptw1, cfw1, ptw2);

    for (int i = 0; i < nch; i++) {
        k_conv<<<(chunk + 7) / 8, 128, 4 * 2016 * 8>>>(
            board, c1b, c2b, c3b, qp, B, i * chunk);
        cudaEventRecord(evc[i], 0);
    }
    for (int i = 0; i < nch; i++) {
        cudaStreamWaitEvent(s2, evc[i], 0);
        k_fc1<<<chunk / 64, 256, FC1_SMEM, s2>>>(
            ptb1, cfb1, ptb2, ptw3, ptb3, cfw2, cfb2,
            (float*)d_out, i * chunk);
    }
    cudaEventRecord(evj, s2);
    cudaStreamWaitEvent(0, evj, 0);
}

// round 15
// speedup vs baseline: 1.1750x; 1.0892x over previous
#include <cuda_runtime.h>
#include <math.h>

#define BATCH_MAX 65536
#define FEAT 584
#define FEAT_PAD 592

typedef unsigned long long u64t;

__device__ float g_feats[(size_t)BATCH_MAX * FEAT_PAD + 16]; // +16 pad for float4 tails

// Weight copies
__device__ float g_w1t[27 * 16];            // [tap][co]
__device__ unsigned g_bfrag[74 * 24 * 64];  // fc1 B, tf32 fragment-major
__device__ unsigned g_w2frag[16 * 8 * 64];  // heads W2, tf32 fragment-major
__device__ unsigned g_w3frag[36 * 8 * 64];  // conv3 W3, tf32 fragment-major
__device__ unsigned g_w2cfrag[18 * 4 * 64]; // conv2 W2, tf32 fragment-major

// ---- packed f32x2 helpers -------------------------------------------------
__device__ __forceinline__ float2 ffma2(float2 a, float2 b, float2 c) {
    u64t ua = *(u64t*)&a, ub = *(u64t*)&b, uc = *(u64t*)&c, ud;
    asm("fma.rn.f32x2 %0, %1, %2, %3;" : "=l"(ud) : "l"(ua), "l"(ub), "l"(uc));
    return *(float2*)&ud;
}
__device__ __forceinline__ float2 bcast2(float w) { return make_float2(w, w); }
__device__ __forceinline__ float2 fmax2(float2 a, float2 b) {
    return make_float2(fmaxf(a.x, b.x), fmaxf(a.y, b.y));
}
__device__ __forceinline__ unsigned f2tf32(float v) {
    unsigned o; asm("cvt.rna.tf32.f32 %0, %1;" : "=r"(o) : "f"(v)); return o;
}
#define MMA_TF32(accp, a0, a1, a2, a3, bx, by)                                \
    asm volatile(                                                             \
        "mma.sync.aligned.m16n8k8.row.col.f32.tf32.tf32.f32 "                 \
        "{%0,%1,%2,%3}, {%4,%5,%6,%7}, {%8,%9}, {%0,%1,%2,%3};"               \
        : "+f"((accp)[0]), "+f"((accp)[1]), "+f"((accp)[2]), "+f"((accp)[3])  \
        : "r"(a0), "r"(a1), "r"(a2), "r"(a3), "r"(bx), "r"(by))

// ---------------------------------------------------------------------------
// Kernel 0a: conv weight pre-bakes (needed before k_conv).
// ---------------------------------------------------------------------------
__global__ void k_prep_conv(const float* __restrict__ w1,
                            const float* __restrict__ w2,
                            const float* __restrict__ w3)
{
    const int idx = blockIdx.x * 256 + threadIdx.x;

    if (idx < 432) {                       // conv1 transpose
        int co = idx / 27, r = idx - co * 27;
        g_w1t[r * 16 + co] = w1[idx];
    }
    if (idx < 36 * 8 * 64) {               // conv3 W3
        const int r = idx & 1;
        const int l = (idx >> 1) & 31;
        const int j = (idx >> 6) & 7;
        const int k8 = idx >> 9;
        const int k = k8 * 8 + r * 4 + (l & 3);
        const int n = j * 8 + (l >> 2);
        g_w3frag[idx] = f2tf32(w3[(size_t)n * 288 + k]);
    }
    if (idx < 18 * 4 * 64) {               // conv2 W2
        const int r = idx & 1;
        const int l = (idx >> 1) & 31;
        const int j = (idx >> 6) & 3;
        const int k8 = idx >> 8;
        const int k = k8 * 8 + r * 4 + (l & 3);
        const int n = j * 8 + (l >> 2);
        g_w2cfrag[idx] = f2tf32(w2[(size_t)n * 144 + k]);
    }
}

// ---------------------------------------------------------------------------
// Kernel 0b: fc1/heads weight pre-bakes (needed before k_fc1; runs on s2
// concurrent with the first conv chunks).
// ---------------------------------------------------------------------------
__global__ void k_prep_fc(const float* __restrict__ ptw1,
                          const float* __restrict__ cfw1,
                          const float* __restrict__ ptw2)
{
    const int idx = blockIdx.x * 256 + threadIdx.x;

    if (idx < 74 * 24 * 64) {              // fc1 B
        const int r = idx & 1;
        const int l = (idx >> 1) & 31;
        const int j = (idx >> 6) % 24;
        const int K8 = idx / (24 * 64);
        const int k = K8 * 8 + r * 4 + (l & 3);
        const int n = j * 8 + (l >> 2);
        float v = 0.f;
        if (k < 584)
            v = (n < 128) ? ptw1[(size_t)k * 128 + n] : cfw1[(size_t)k * 64 + (n - 128)];
        g_bfrag[idx] = f2tf32(v);
    }
    if (idx < 16 * 8 * 64) {               // heads W2
        const int r = idx & 1;
        const int l = (idx >> 1) & 31;
        const int j = (idx >> 6) & 7;
        const int k8 = idx >> 9;
        const int k = k8 * 8 + r * 4 + (l & 3);
        const int n = j * 8 + (l >> 2);
        g_w2frag[idx] = f2tf32(ptw2[(size_t)k * 64 + n]);
    }
}

// ---------------------------------------------------------------------------
// conv2 row mapping: r = s*36 + q*4 + sub
// ---------------------------------------------------------------------------
__device__ __forceinline__ int c2_rowbase(int r)
{
    const int s = r / 36, rem = r - 36 * s;
    const int q = rem >> 2, sub = rem & 3;
    const int qy = q / 3, qx = q - 3 * qy;
    const int py = 2 * qy + (sub >> 1);
    const int px = 2 * qx + (sub & 1);
    return (s >> 1) * 4032 + 384 + (s & 1) + 2 * (py * 8 + px);
}

// ---------------------------------------------------------------------------
// conv2 mma tile (fused relu+pool)
// ---------------------------------------------------------------------------
__device__ __forceinline__ void conv2_tile(
    float* smf, const int* offk2, const float* b2s,
    int mt, int g, int tg, int lane)
{
    const int r1 = mt * 16 + g, r2 = r1 + 8;
    const int base1 = c2_rowbase(r1), base2 = c2_rowbase(r2);

    float acc[4][4];
    #pragma unroll
    for (int j = 0; j < 4; j++)
        #pragma unroll
        for (int q = 0; q < 4; q++) acc[j][q] = 0.f;

    #pragma unroll 3
    for (int k8 = 0; k8 < 18; k8++) {
        const int oa = offk2[k8 * 8 + tg];
        const int oc = offk2[k8 * 8 + tg + 4];
        const unsigned a0 = f2tf32(smf[base1 + oa]);
        const unsigned a1 = f2tf32(smf[base2 + oa]);
        const unsigned a2 = f2tf32(smf[base1 + oc]);
        const unsigned a3 = f2tf32(smf[base2 + oc]);
        #pragma unroll
        for (int j = 0; j < 4; j++) {
            const uint2 b = __ldg((const uint2*)g_w2cfrag + (k8 * 4 + j) * 32 + lane);
            MMA_TF32(acc[j], a0, a1, a2, a3, b.x, b.y);
        }
    }

    #pragma unroll
    for (int j = 0; j < 4; j++)
        #pragma unroll
        for (int q = 0; q < 4; q++) {
            float v = acc[j][q];
            v = fmaxf(v, __shfl_xor_sync(0xffffffffu, v, 4));
            v = fmaxf(v, __shfl_xor_sync(0xffffffffu, v, 8));
            acc[j][q] = v;
        }
    if ((g & 3) == 0) {
        #pragma unroll
        for (int j = 0; j < 4; j++)
            #pragma unroll
            for (int q = 0; q < 4; q++) {
                const int n = j * 8 + tg * 2 + (q & 1);
                const int r = (q < 2) ? r1 : r2;
                const int gq = r >> 2;
                const int s = gq / 9, qp = gq - 9 * s;
                const int py = qp / 3, px = qp - 3 * py;
                smf[(s >> 1) * 4032 + 2432 + (s & 1)
                    + 2 * (n * 25 + (py + 1) * 5 + (px + 1))]
                    = fmaxf(acc[j][q] + b2s[n], 0.f);
            }
    }
}

// ---------------------------------------------------------------------------
// conv3 mma tile
// ---------------------------------------------------------------------------
template<int NN>
__device__ __forceinline__ void conv3_tile(
    float* smf, const int* offk, const float* b3s,
    int mt, int n8lo, int g, int tg, int lane)
{
    const int r1 = mt * 16 + g, r2 = r1 + 8;
    const bool v1 = (r1 < 72), v2 = (r2 < 72);
    int base1 = 0, base2 = 0;
    if (v1) {
        const int s = r1 / 9, p = r1 - 9 * s;
        base1 = (s >> 1) * 4032 + 2432 + (s & 1) + 2 * ((p / 3) * 5 + (p % 3));
    }
    if (v2) {
        const int s = r2 / 9, p = r2 - 9 * s;
        base2 = (s >> 1) * 4032 + 2432 + (s & 1) + 2 * ((p / 3) * 5 + (p % 3));
    }

    float acc[NN][4];
    #pragma unroll
    for (int j = 0; j < NN; j++)
        #pragma unroll
        for (int q = 0; q < 4; q++) acc[j][q] = 0.f;

    #pragma unroll 4
    for (int k8 = 0; k8 < 36; k8++) {
        const int oa = offk[k8 * 8 + tg] * 2;
        const int oc = offk[k8 * 8 + tg + 4] * 2;
        const unsigned a0 = v1 ? f2tf32(smf[base1 + oa]) : 0u;
        const unsigned a1 = v2 ? f2tf32(smf[base2 + oa]) : 0u;
        const unsigned a2 = v1 ? f2tf32(smf[base1 + oc]) : 0u;
        const unsigned a3 = v2 ? f2tf32(smf[base2 + oc]) : 0u;
        #pragma unroll
        for (int j = 0; j < NN; j++) {
            const uint2 b = __ldg((const uint2*)g_w3frag + (k8 * 8 + n8lo + j) * 32 + lane);
            MMA_TF32(acc[j], a0, a1, a2, a3, b.x, b.y);
        }
    }
    #pragma unroll
    for (int j = 0; j < NN; j++)
        #pragma unroll
        for (int q = 0; q < 4; q++) {
            const int n = (n8lo + j) * 8 + tg * 2 + (q & 1);
            const int r = (q < 2) ? r1 : r2;
            if (r < 72)
                smf[(r / 18) * 4032 + 384 + (r % 18) * 65 + n] =
                    fmaxf(acc[j][q] + b3s[n], 0.f);
        }
}

// ---------------------------------------------------------------------------
// Kernel 1: conv pipeline + quantum sim (round-12 verbatim).
// ---------------------------------------------------------------------------
__global__ __launch_bounds__(128) void k_conv(
    const float* __restrict__ board,
    const float* __restrict__ b1,
    const float* __restrict__ b2,
    const float* __restrict__ b3,
    const float* __restrict__ qp, int nsamp, int s_off)
{
    extern __shared__ float2 smc[];
    float* smf = (float*)smc;
    const int tid = threadIdx.x;
    const int warp = tid >> 5, lane = tid & 31;
    const int pidx = blockIdx.x * 4 + warp;
    const int s0 = s_off + 2 * pidx;
    const bool active = (s0 < nsamp);
    const bool has2 = (s0 + 1 < nsamp);

    float2* inp = smc + (size_t)warp * 2016;
    float2* h1p = inp + 192;

    for (int i = lane; i < 2016; i += 32) inp[i] = make_float2(0.f, 0.f);
    __syncwarp();

    if (active) {
        const float* bs0 = board + (size_t)s0 * 108;
        const float* bs1 = has2 ? bs0 + 108 : bs0;

        for (int i = lane; i < 108; i += 32) {
            int ci = i / 36, r = i - ci * 36;
            int y = r / 6, x = r - y * 6;
            inp[ci * 64 + (y + 1) * 8 + (x + 1)] = make_float2(bs0[i], bs1[i]);
        }

        if (lane < 16) {
            const int smp = lane >> 3, qb = lane & 7;
            const int sg = s0 + smp;
            if (sg < nsamp) {
                const float* bq = board + (size_t)sg * 108;
                float xv = bq[qb], xn = bq[(qb + 1) & 7];
                float q = 0.f;
                #pragma unroll
                for (int l = 0; l < 3; l++) {
                    float r0 = __ldg(qp + (l * 8 + qb) * 3 + 0);
                    float r1 = __ldg(qp + (l * 8 + qb) * 3 + 1);
                    float r2 = __ldg(qp + (l * 8 + qb) * 3 + 2);
                    q = sinf(r0 * xv) * cosf(r1 * xn) + tanhf(r2 * q);
                }
                g_feats[(size_t)sg * FEAT_PAD + 576 + qb] = q;
                g_feats[(size_t)sg * FEAT_PAD + 584 + qb] = 0.f;
            }
        }
        __syncwarp();

        {   // conv1 (round-12 scalar version — high-ILP)
            const int co = lane & 15, half = lane >> 4;
            float2 w[27];
            #pragma unroll
            for (int i = 0; i < 27; i++) w[i] = bcast2(__ldg(g_w1t + i * 16 + co));
            const float2 bias = bcast2(__ldg(b1 + co));
            #pragma unroll
            for (int p = 0; p < 18; p++) {
                const int yy = half * 3 + p / 6;
                const int xx = p % 6;
                const int y8 = yy * 8;
                float2 a = bias;
                #pragma unroll
                for (int ci = 0; ci < 3; ci++)
                    #pragma unroll
                    for (int ky = 0; ky < 3; ky++)
                        #pragma unroll
                        for (int kx = 0; kx < 3; kx++)
                            a = ffma2(inp[ci * 64 + y8 + ky * 8 + xx + kx],
                                      w[ci * 9 + ky * 3 + kx], a);
                h1p[co * 64 + y8 + 8 + xx + 1] = fmax2(a, make_float2(0.f, 0.f));
            }
        }
    }
    __syncthreads();

    for (int i = tid; i < 288; i += 128) {
        const int ci = i / 9, tap = i - ci * 9;
        ((int*)smf)[i] = ci * 25 + (tap / 3) * 5 + (tap % 3);
    }
    for (int i = tid; i < 144; i += 128) {
        const int ci = i / 9, tap = i - ci * 9;
        ((int*)(smf + 4032))[i] = 2 * (ci * 64 + (tap / 3) * 8 + (tap % 3));
    }
    if (tid < 64) smf[288 + tid] = __ldg(b3 + tid);
    if (tid < 32) smf[4200 + tid] = __ldg(b2 + tid);
    __syncthreads();

    {   // conv2 via mma
        const int g = lane >> 2, tg = lane & 3;
        const int* offk2 = (const int*)(smf + 4032);
        const float* b2s = smf + 4200;
        conv2_tile(smf, offk2, b2s, warp,      g, tg, lane);
        conv2_tile(smf, offk2, b2s, warp + 4,  g, tg, lane);
        conv2_tile(smf, offk2, b2s, warp + 8,  g, tg, lane);
        conv2_tile(smf, offk2, b2s, warp + 12, g, tg, lane);
        if (warp < 2) conv2_tile(smf, offk2, b2s, 16 + warp, g, tg, lane);
    }
    __syncthreads();

    {   // conv3 via mma
        const int g = lane >> 2, tg = lane & 3;
        const int* offk = (const int*)smf;
        const float* b3s = smf + 288;
        conv3_tile<8>(smf, offk, b3s, warp, 0, g, tg, lane);
        conv3_tile<2>(smf, offk, b3s, 4, 2 * warp, g, tg, lane);
    }
    __syncthreads();

    {   // writeback
        const int s = tid >> 4, li = tid & 15;
        const int sg = s_off + blockIdx.x * 8 + s;
        if (sg < nsamp) {
            float* f = g_feats + (size_t)sg * FEAT_PAD;
            for (int i = li; i < 576; i += 16) {
                const int co = i / 9, p = i - 9 * co;
                const int r = s * 9 + p;
                f[i] = smf[(r / 18) * 4032 + 384 + (r % 18) * 65 + co];
            }
        }
    }
}

// ---------------------------------------------------------------------------
// Kernel 2: BM=64, double-buffered tf32 GEMM + tensor-core heads (round-12).
// ---------------------------------------------------------------------------
#define FC1_SMEM (12992 * 4)

__global__ __launch_bounds__(256) void k_fc1(
    const float* __restrict__ ptb1, const float* __restrict__ cfb1,
    const float* __restrict__ ptb2,
    const float* __restrict__ ptw3, const float* __restrict__ ptb3,
    const float* __restrict__ cfw2, const float* __restrict__ cfb2,
    float* __restrict__ out, int m_off)
{
    extern __shared__ float sfc[];
    unsigned* A_s = (unsigned*)sfc;            // 2 x 1024
    unsigned* B_s = (unsigned*)(sfc + 2048);   // 2 x 3072
    float* C1s    = sfc;                       // 12544 (post-GEMM alias)
    float* BiasS  = sfc + 12544;               // 192
    float* W3s    = sfc + 12736;               // 128
    float* CW2s   = sfc + 12864;               // 64
    float* B2s    = sfc + 12928;               // 64

    const int t = threadIdx.x;
    const int m0 = m_off + blockIdx.x * 64;
    const int warp = t >> 5, lane = t & 31;
    const int wm = warp >> 1, wn = warp & 1;
    const int g = lane >> 2, tg = lane & 3;

    if (t < 192) BiasS[t] = (t < 128) ? __ldg(ptb1 + t) : __ldg(cfb1 + t - 128);
    if (t < 128) W3s[t] = __ldg(ptw3 + t);
    if (t < 64)  { CW2s[t] = __ldg(cfw2 + t); B2s[t] = __ldg(ptb2 + t); }

    float acc[12][4];
    #pragma unroll
    for (int j = 0; j < 12; j++)
        #pragma unroll
        for (int r = 0; r < 4; r++) acc[j][r] = 0.f;

    const bool aload = (t < 128);
    const int am = t >> 1;
    const int kcA = t & 1;
    const int rA = am & 15, mtA = (am >> 4) & 3;
    const int baseA = ((kcA * 4 + mtA) * 32 + (rA & 7) * 4) * 4 + (rA >> 3);
    const float* arow = g_feats + (size_t)(m0 + (am & 63)) * FEAT_PAD + kcA * 8;

    float4 av0 = make_float4(0.f, 0.f, 0.f, 0.f);
    float4 av1 = av0;
    if (aload) { av0 = *(const float4*)(arow); av1 = *(const float4*)(arow + 4); }
    uint4 bv0 = *(const uint4*)(g_bfrag + t * 12);
    uint4 bv1 = *(const uint4*)(g_bfrag + t * 12 + 4);
    uint4 bv2 = *(const uint4*)(g_bfrag + t * 12 + 8);

    int p = 0;
    for (int it = 0; it < 37; ++it) {
        unsigned* Ab = A_s + p * 1024;
        unsigned* Bb = B_s + p * 3072;
        if (aload) {
            Ab[baseA + 0 * 4 + 0] = f2tf32(av0.x);
            Ab[baseA + 1 * 4 + 0] = f2tf32(av0.y);
            Ab[baseA + 2 * 4 + 0] = f2tf32(av0.z);
            Ab[baseA + 3 * 4 + 0] = f2tf32(av0.w);
            Ab[baseA + 0 * 4 + 2] = f2tf32(av1.x);
            Ab[baseA + 1 * 4 + 2] = f2tf32(av1.y);
            Ab[baseA + 2 * 4 + 2] = f2tf32(av1.z);
            Ab[baseA + 3 * 4 + 2] = f2tf32(av1.w);
        }
        *(uint4*)(Bb + t * 12)     = bv0;
        *(uint4*)(Bb + t * 12 + 4) = bv1;
        *(uint4*)(Bb + t * 12 + 8) = bv2;
        __syncthreads();
        if (it < 36) {
            if (aload) {
                av0 = *(const float4*)(arow + (it + 1) * 16);
                av1 = *(const float4*)(arow + (it + 1) * 16 + 4);
            }
            const unsigned* bsrc = g_bfrag + (it + 1) * 3072 + t * 12;
            bv0 = *(const uint4*)(bsrc);
            bv1 = *(const uint4*)(bsrc + 4);
            bv2 = *(const uint4*)(bsrc + 8);
        }
        #pragma unroll
        for (int kc = 0; kc < 2; kc++) {
            const uint4 v = *(const uint4*)(Ab + ((kc * 4 + wm) * 32 + lane) * 4);
            #pragma unroll
            for (int j = 0; j < 12; j++) {
                const uint2 b = *(const uint2*)(Bb + ((kc * 24 + wn * 12 + j) * 32 + lane) * 2);
                MMA_TF32(acc[j], v.x, v.y, v.z, v.w, b.x, b.y);
            }
        }
        p ^= 1;
    }
    __syncthreads();

    #pragma unroll
    for (int j = 0; j < 12; j++)
        #pragma unroll
        for (int r = 0; r < 4; r++) {
            const int m = wm * 16 + ((r >> 1) << 3) + g;
            const int n = wn * 96 + j * 8 + tg * 2 + (r & 1);
            C1s[m * 196 + n] = fmaxf(acc[j][r] + BiasS[n], 0.f);
        }
    __syncthreads();

    if (warp < 4) {
        const int base = warp * 16;
        float hacc[8][4];
        #pragma unroll
        for (int j = 0; j < 8; j++)
            #pragma unroll
            for (int r = 0; r < 4; r++) hacc[j][r] = 0.f;

        #pragma unroll 4
        for (int k8 = 0; k8 < 16; k8++) {
            const float* cA = C1s + base * 196 + k8 * 8;
            const unsigned a0 = f2tf32(cA[g * 196 + tg]);
            const unsigned a1 = f2tf32(cA[(g + 8) * 196 + tg]);
            const unsigned a2 = f2tf32(cA[g * 196 + tg + 4]);
            const unsigned a3 = f2tf32(cA[(g + 8) * 196 + tg + 4]);
            #pragma unroll
            for (int j = 0; j < 8; j++) {
                const uint2 b = __ldg((const uint2*)g_w2frag + (k8 * 8 + j) * 32 + lane);
                MMA_TF32(hacc[j], a0, a1, a2, a3, b.x, b.y);
            }
        }

        float l0g = 0.f, l1g = 0.f, l0h = 0.f, l1h = 0.f;
        #pragma unroll
        for (int j = 0; j < 8; j++)
            #pragma unroll
            for (int r = 0; r < 4; r++) {
                const int n = j * 8 + tg * 2 + (r & 1);
                const float v = fmaxf(hacc[j][r] + B2s[n], 0.f);
                const float w30 = W3s[n * 2], w31 = W3s[n * 2 + 1];
                if (r < 2) { l0g = fmaf(v, w30, l0g); l1g = fmaf(v, w31, l1g); }
                else       { l0h = fmaf(v, w30, l0h); l1h = fmaf(v, w31, l1h); }
            }
        #pragma unroll
        for (int off = 1; off <= 2; off <<= 1) {
            l0g += __shfl_xor_sync(0xffffffffu, l0g, off);
            l1g += __shfl_xor_sync(0xffffffffu, l1g, off);
            l0h += __shfl_xor_sync(0xffffffffu, l0h, off);
            l1h += __shfl_xor_sync(0xffffffffu, l1h, off);
        }
        if (tg == 0) {
            const float b30 = __ldg(ptb3 + 0), b31 = __ldg(ptb3 + 1);
            {
                const float l0 = l0g + b30, l1 = l1g + b31;
                const float mx = fmaxf(l0, l1);
                const float e0 = expf(l0 - mx), e1 = expf(l1 - mx);
                const float inv = 1.f / (e0 + e1);
                out[(size_t)(m0 + base + g) * 3 + 0] = e0 * inv;
                out[(size_t)(m0 + base + g) * 3 + 1] = e1 * inv;
            }
            {
                const float l0 = l0h + b30, l1 = l1h + b31;
                const float mx = fmaxf(l0, l1);
                const float e0 = expf(l0 - mx), e1 = expf(l1 - mx);
                const float inv = 1.f / (e0 + e1);
                out[(size_t)(m0 + base + g + 8) * 3 + 0] = e0 * inv;
                out[(size_t)(m0 + base + g + 8) * 3 + 1] = e1 * inv;
            }
        }
    } else {
        const int base = (warp - 4) * 16;
        for (int i = 0; i < 16; i++) {
            const int ml = base + i;
            const float* c1 = C1s + ml * 196;
            float cc = c1[128 + lane] * CW2s[lane] + c1[160 + lane] * CW2s[lane + 32];
            #pragma unroll
            for (int off = 16; off; off >>= 1)
                cc += __shfl_xor_sync(0xffffffffu, cc, off);
            if (lane == 0)
                out[(size_t)(m0 + ml) * 3 + 2] =
                    1.f / (1.f + expf(-(cc + __ldg(cfb2))));
        }
    }
}

// ---------------------------------------------------------------------------
// Launch: 8-chunk conv->fc1 pipeline on two streams. fc1 weight bake runs on
// s2 concurrent with the first conv chunks.
// ---------------------------------------------------------------------------
extern "C" void kernel_launch(void* const* d_in, const int* in_sizes, int n_in,
                              void* d_out, int out_size)
{
    const float* board = (const float*)d_in[0];
    // d_in[1] = target_positions (int64) — mathematically unused
    const float* c1w = (const float*)d_in[2];  const float* c1b = (const float*)d_in[3];
    const float* c2w = (const float*)d_in[4];  const float* c2b = (const float*)d_in[5];
    const float* c3w = (const float*)d_in[6];  const float* c3b = (const float*)d_in[7];
    const float* qp  = (const float*)d_in[8];
    const float* ptw1 = (const float*)d_in[9];  const float* ptb1 = (const float*)d_in[10];
    const float* ptw2 = (const float*)d_in[11]; const float* ptb2 = (const float*)d_in[12];
    const float* ptw3 = (const float*)d_in[13]; const float* ptb3 = (const float*)d_in[14];
    const float* cfw1 = (const float*)d_in[15]; const float* cfb1 = (const float*)d_in[16];
    const float* cfw2 = (const float*)d_in[17]; const float* cfb2 = (const float*)d_in[18];

    int B = in_sizes[0] / 108;
    if (B > BATCH_MAX) B = BATCH_MAX;

    static bool init_done = false;
    static cudaStream_t s2;
    static cudaEvent_t evc[8], evj;
    if (!init_done) {
        cudaFuncSetAttribute(k_conv, cudaFuncAttributeMaxDynamicSharedMemorySize, 4 * 2016 * 8);
        cudaFuncSetAttribute(k_fc1, cudaFuncAttributeMaxDynamicSharedMemorySize, FC1_SMEM);
        cudaStreamCreateWithFlags(&s2, cudaStreamNonBlocking);
        for (int i = 0; i < 8; i++)
            cudaEventCreateWithFlags(&evc[i], cudaEventDisableTiming);
        cudaEventCreateWithFlags(&evj, cudaEventDisableTiming);
        init_done = true;
    }

    // chunking: 8 chunks when cleanly divisible (conv: 8/blk, fc1: 64/blk)
    const int nch = (B % (512 * 8) == 0) ? 8 : 1;
    const int chunk = B / nch;

    // fc1 weight bake on s2 (overlaps conv chunks); conv bake on stream 0.
    k_prep_fc<<<(74 * 24 * 64 + 255) / 256, 256, 0, s2>>>(ptw1, cfw1, ptw2);
    k_prep_conv<<<72, 256>>>(c1w, c2w, c3w);

    for (int i = 0; i < nch; i++) {
        k_conv<<<(chunk + 7) / 8, 128, 4 * 2016 * 8>>>(
            board, c1b, c2b, c3b, qp, B, i * chunk);
        cudaEventRecord(evc[i], 0);
    }
    for (int i = 0; i < nch; i++) {
        cudaStreamWaitEvent(s2, evc[i], 0);
        k_fc1<<<chunk / 64, 256, FC1_SMEM, s2>>>(
            ptb1, cfb1, ptb2, ptw3, ptb3, cfw2, cfb2,
            (float*)d_out, i * chunk);
    }
    cudaEventRecord(evj, s2);
    cudaStreamWaitEvent(0, evj, 0);
}

// round 16
// speedup vs baseline: 1.2567x; 1.0695x over previous
#include <cuda_runtime.h>
#include <math.h>

#define BATCH_MAX 65536
#define FEAT 584
#define FEAT_PAD 592

typedef unsigned long long u64t;

__device__ float g_feats[(size_t)BATCH_MAX * FEAT_PAD + 16]; // +16 pad for float4 tails

// Weight copies
__device__ float g_w1t[27 * 16];            // [tap][co]
__device__ unsigned g_bfrag[74 * 24 * 64];  // fc1 B, tf32 fragment-major
__device__ unsigned g_w2frag[16 * 8 * 64];  // heads W2, tf32 fragment-major
__device__ unsigned g_w3frag[36 * 8 * 64];  // conv3 W3, tf32 fragment-major
__device__ unsigned g_w2cfrag[18 * 4 * 64]; // conv2 W2, tf32 fragment-major

// ---- packed f32x2 helpers -------------------------------------------------
__device__ __forceinline__ float2 ffma2(float2 a, float2 b, float2 c) {
    u64t ua = *(u64t*)&a, ub = *(u64t*)&b, uc = *(u64t*)&c, ud;
    asm("fma.rn.f32x2 %0, %1, %2, %3;" : "=l"(ud) : "l"(ua), "l"(ub), "l"(uc));
    return *(float2*)&ud;
}
__device__ __forceinline__ float2 bcast2(float w) { return make_float2(w, w); }
__device__ __forceinline__ float2 fmax2(float2 a, float2 b) {
    return make_float2(fmaxf(a.x, b.x), fmaxf(a.y, b.y));
}
__device__ __forceinline__ unsigned f2tf32(float v) {
    unsigned o; asm("cvt.rna.tf32.f32 %0, %1;" : "=r"(o) : "f"(v)); return o;
}
#define MMA_TF32(accp, a0, a1, a2, a3, bx, by)                                \
    asm volatile(                                                             \
        "mma.sync.aligned.m16n8k8.row.col.f32.tf32.tf32.f32 "                 \
        "{%0,%1,%2,%3}, {%4,%5,%6,%7}, {%8,%9}, {%0,%1,%2,%3};"               \
        : "+f"((accp)[0]), "+f"((accp)[1]), "+f"((accp)[2]), "+f"((accp)[3])  \
        : "r"(a0), "r"(a1), "r"(a2), "r"(a3), "r"(bx), "r"(by))

// ---------------------------------------------------------------------------
// Kernel 0a: conv weight pre-bakes (needed before k_conv).
// ---------------------------------------------------------------------------
__global__ void k_prep_conv(const float* __restrict__ w1,
                            const float* __restrict__ w2,
                            const float* __restrict__ w3)
{
    const int idx = blockIdx.x * 256 + threadIdx.x;

    if (idx < 432) {                       // conv1 transpose
        int co = idx / 27, r = idx - co * 27;
        g_w1t[r * 16 + co] = w1[idx];
    }
    if (idx < 36 * 8 * 64) {               // conv3 W3
        const int r = idx & 1;
        const int l = (idx >> 1) & 31;
        const int j = (idx >> 6) & 7;
        const int k8 = idx >> 9;
        const int k = k8 * 8 + r * 4 + (l & 3);
        const int n = j * 8 + (l >> 2);
        g_w3frag[idx] = f2tf32(w3[(size_t)n * 288 + k]);
    }
    if (idx < 18 * 4 * 64) {               // conv2 W2
        const int r = idx & 1;
        const int l = (idx >> 1) & 31;
        const int j = (idx >> 6) & 3;
        const int k8 = idx >> 8;
        const int k = k8 * 8 + r * 4 + (l & 3);
        const int n = j * 8 + (l >> 2);
        g_w2cfrag[idx] = f2tf32(w2[(size_t)n * 144 + k]);
    }
}

// ---------------------------------------------------------------------------
// Kernel 0b: fc1/heads weight pre-bakes (on s2, overlapping conv chunks).
// ---------------------------------------------------------------------------
__global__ void k_prep_fc(const float* __restrict__ ptw1,
                          const float* __restrict__ cfw1,
                          const float* __restrict__ ptw2)
{
    const int idx = blockIdx.x * 256 + threadIdx.x;

    if (idx < 74 * 24 * 64) {              // fc1 B
        const int r = idx & 1;
        const int l = (idx >> 1) & 31;
        const int j = (idx >> 6) % 24;
        const int K8 = idx / (24 * 64);
        const int k = K8 * 8 + r * 4 + (l & 3);
        const int n = j * 8 + (l >> 2);
        float v = 0.f;
        if (k < 584)
            v = (n < 128) ? ptw1[(size_t)k * 128 + n] : cfw1[(size_t)k * 64 + (n - 128)];
        g_bfrag[idx] = f2tf32(v);
    }
    if (idx < 16 * 8 * 64) {               // heads W2
        const int r = idx & 1;
        const int l = (idx >> 1) & 31;
        const int j = (idx >> 6) & 7;
        const int k8 = idx >> 9;
        const int k = k8 * 8 + r * 4 + (l & 3);
        const int n = j * 8 + (l >> 2);
        g_w2frag[idx] = f2tf32(ptw2[(size_t)k * 64 + n]);
    }
}

// ---------------------------------------------------------------------------
// conv2 row mapping: r = s*36 + q*4 + sub
// ---------------------------------------------------------------------------
__device__ __forceinline__ int c2_rowbase(int r)
{
    const int s = r / 36, rem = r - 36 * s;
    const int q = rem >> 2, sub = rem & 3;
    const int qy = q / 3, qx = q - 3 * qy;
    const int py = 2 * qy + (sub >> 1);
    const int px = 2 * qx + (sub & 1);
    return (s >> 1) * 4032 + 384 + (s & 1) + 2 * (py * 8 + px);
}

// ---------------------------------------------------------------------------
// conv2 mma tile (fused relu+pool)
// ---------------------------------------------------------------------------
__device__ __forceinline__ void conv2_tile(
    float* smf, const int* offk2, const float* b2s,
    int mt, int g, int tg, int lane)
{
    const int r1 = mt * 16 + g, r2 = r1 + 8;
    const int base1 = c2_rowbase(r1), base2 = c2_rowbase(r2);

    float acc[4][4];
    #pragma unroll
    for (int j = 0; j < 4; j++)
        #pragma unroll
        for (int q = 0; q < 4; q++) acc[j][q] = 0.f;

    #pragma unroll 3
    for (int k8 = 0; k8 < 18; k8++) {
        const int oa = offk2[k8 * 8 + tg];
        const int oc = offk2[k8 * 8 + tg + 4];
        const unsigned a0 = f2tf32(smf[base1 + oa]);
        const unsigned a1 = f2tf32(smf[base2 + oa]);
        const unsigned a2 = f2tf32(smf[base1 + oc]);
        const unsigned a3 = f2tf32(smf[base2 + oc]);
        #pragma unroll
        for (int j = 0; j < 4; j++) {
            const uint2 b = __ldg((const uint2*)g_w2cfrag + (k8 * 4 + j) * 32 + lane);
            MMA_TF32(acc[j], a0, a1, a2, a3, b.x, b.y);
        }
    }

    #pragma unroll
    for (int j = 0; j < 4; j++)
        #pragma unroll
        for (int q = 0; q < 4; q++) {
            float v = acc[j][q];
            v = fmaxf(v, __shfl_xor_sync(0xffffffffu, v, 4));
            v = fmaxf(v, __shfl_xor_sync(0xffffffffu, v, 8));
            acc[j][q] = v;
        }
    if ((g & 3) == 0) {
        #pragma unroll
        for (int j = 0; j < 4; j++)
            #pragma unroll
            for (int q = 0; q < 4; q++) {
                const int n = j * 8 + tg * 2 + (q & 1);
                const int r = (q < 2) ? r1 : r2;
                const int gq = r >> 2;
                const int s = gq / 9, qp = gq - 9 * s;
                const int py = qp / 3, px = qp - 3 * py;
                smf[(s >> 1) * 4032 + 2432 + (s & 1)
                    + 2 * (n * 25 + (py + 1) * 5 + (px + 1))]
                    = fmaxf(acc[j][q] + b2s[n], 0.f);
            }
    }
}

// ---------------------------------------------------------------------------
// conv3 mma tile
// ---------------------------------------------------------------------------
template<int NN>
__device__ __forceinline__ void conv3_tile(
    float* smf, const int* offk, const float* b3s,
    int mt, int n8lo, int g, int tg, int lane)
{
    const int r1 = mt * 16 + g, r2 = r1 + 8;
    const bool v1 = (r1 < 72), v2 = (r2 < 72);
    int base1 = 0, base2 = 0;
    if (v1) {
        const int s = r1 / 9, p = r1 - 9 * s;
        base1 = (s >> 1) * 4032 + 2432 + (s & 1) + 2 * ((p / 3) * 5 + (p % 3));
    }
    if (v2) {
        const int s = r2 / 9, p = r2 - 9 * s;
        base2 = (s >> 1) * 4032 + 2432 + (s & 1) + 2 * ((p / 3) * 5 + (p % 3));
    }

    float acc[NN][4];
    #pragma unroll
    for (int j = 0; j < NN; j++)
        #pragma unroll
        for (int q = 0; q < 4; q++) acc[j][q] = 0.f;

    #pragma unroll 4
    for (int k8 = 0; k8 < 36; k8++) {
        const int oa = offk[k8 * 8 + tg] * 2;
        const int oc = offk[k8 * 8 + tg + 4] * 2;
        const unsigned a0 = v1 ? f2tf32(smf[base1 + oa]) : 0u;
        const unsigned a1 = v2 ? f2tf32(smf[base2 + oa]) : 0u;
        const unsigned a2 = v1 ? f2tf32(smf[base1 + oc]) : 0u;
        const unsigned a3 = v2 ? f2tf32(smf[base2 + oc]) : 0u;
        #pragma unroll
        for (int j = 0; j < NN; j++) {
            const uint2 b = __ldg((const uint2*)g_w3frag + (k8 * 8 + n8lo + j) * 32 + lane);
            MMA_TF32(acc[j], a0, a1, a2, a3, b.x, b.y);
        }
    }
    #pragma unroll
    for (int j = 0; j < NN; j++)
        #pragma unroll
        for (int q = 0; q < 4; q++) {
            const int n = (n8lo + j) * 8 + tg * 2 + (q & 1);
            const int r = (q < 2) ? r1 : r2;
            if (r < 72)
                smf[(r / 18) * 4032 + 384 + (r % 18) * 65 + n] =
                    fmaxf(acc[j][q] + b3s[n], 0.f);
        }
}

// ---------------------------------------------------------------------------
// Kernel 1: conv pipeline + quantum sim (round-12 verbatim).
// ---------------------------------------------------------------------------
__global__ __launch_bounds__(128) void k_conv(
    const float* __restrict__ board,
    const float* __restrict__ b1,
    const float* __restrict__ b2,
    const float* __restrict__ b3,
    const float* __restrict__ qp, int nsamp, int s_off)
{
    extern __shared__ float2 smc[];
    float* smf = (float*)smc;
    const int tid = threadIdx.x;
    const int warp = tid >> 5, lane = tid & 31;
    const int pidx = blockIdx.x * 4 + warp;
    const int s0 = s_off + 2 * pidx;
    const bool active = (s0 < nsamp);
    const bool has2 = (s0 + 1 < nsamp);

    float2* inp = smc + (size_t)warp * 2016;
    float2* h1p = inp + 192;

    for (int i = lane; i < 2016; i += 32) inp[i] = make_float2(0.f, 0.f);
    __syncwarp();

    if (active) {
        const float* bs0 = board + (size_t)s0 * 108;
        const float* bs1 = has2 ? bs0 + 108 : bs0;

        for (int i = lane; i < 108; i += 32) {
            int ci = i / 36, r = i - ci * 36;
            int y = r / 6, x = r - y * 6;
            inp[ci * 64 + (y + 1) * 8 + (x + 1)] = make_float2(bs0[i], bs1[i]);
        }

        if (lane < 16) {
            const int smp = lane >> 3, qb = lane & 7;
            const int sg = s0 + smp;
            if (sg < nsamp) {
                const float* bq = board + (size_t)sg * 108;
                float xv = bq[qb], xn = bq[(qb + 1) & 7];
                float q = 0.f;
                #pragma unroll
                for (int l = 0; l < 3; l++) {
                    float r0 = __ldg(qp + (l * 8 + qb) * 3 + 0);
                    float r1 = __ldg(qp + (l * 8 + qb) * 3 + 1);
                    float r2 = __ldg(qp + (l * 8 + qb) * 3 + 2);
                    q = sinf(r0 * xv) * cosf(r1 * xn) + tanhf(r2 * q);
                }
                g_feats[(size_t)sg * FEAT_PAD + 576 + qb] = q;
                g_feats[(size_t)sg * FEAT_PAD + 584 + qb] = 0.f;
            }
        }
        __syncwarp();

        {   // conv1 (round-12 scalar version — high-ILP)
            const int co = lane & 15, half = lane >> 4;
            float2 w[27];
            #pragma unroll
            for (int i = 0; i < 27; i++) w[i] = bcast2(__ldg(g_w1t + i * 16 + co));
            const float2 bias = bcast2(__ldg(b1 + co));
            #pragma unroll
            for (int p = 0; p < 18; p++) {
                const int yy = half * 3 + p / 6;
                const int xx = p % 6;
                const int y8 = yy * 8;
                float2 a = bias;
                #pragma unroll
                for (int ci = 0; ci < 3; ci++)
                    #pragma unroll
                    for (int ky = 0; ky < 3; ky++)
                        #pragma unroll
                        for (int kx = 0; kx < 3; kx++)
                            a = ffma2(inp[ci * 64 + y8 + ky * 8 + xx + kx],
                                      w[ci * 9 + ky * 3 + kx], a);
                h1p[co * 64 + y8 + 8 + xx + 1] = fmax2(a, make_float2(0.f, 0.f));
            }
        }
    }
    __syncthreads();

    for (int i = tid; i < 288; i += 128) {
        const int ci = i / 9, tap = i - ci * 9;
        ((int*)smf)[i] = ci * 25 + (tap / 3) * 5 + (tap % 3);
    }
    for (int i = tid; i < 144; i += 128) {
        const int ci = i / 9, tap = i - ci * 9;
        ((int*)(smf + 4032))[i] = 2 * (ci * 64 + (tap / 3) * 8 + (tap % 3));
    }
    if (tid < 64) smf[288 + tid] = __ldg(b3 + tid);
    if (tid < 32) smf[4200 + tid] = __ldg(b2 + tid);
    __syncthreads();

    {   // conv2 via mma
        const int g = lane >> 2, tg = lane & 3;
        const int* offk2 = (const int*)(smf + 4032);
        const float* b2s = smf + 4200;
        conv2_tile(smf, offk2, b2s, warp,      g, tg, lane);
        conv2_tile(smf, offk2, b2s, warp + 4,  g, tg, lane);
        conv2_tile(smf, offk2, b2s, warp + 8,  g, tg, lane);
        conv2_tile(smf, offk2, b2s, warp + 12, g, tg, lane);
        if (warp < 2) conv2_tile(smf, offk2, b2s, 16 + warp, g, tg, lane);
    }
    __syncthreads();

    {   // conv3 via mma
        const int g = lane >> 2, tg = lane & 3;
        const int* offk = (const int*)smf;
        const float* b3s = smf + 288;
        conv3_tile<8>(smf, offk, b3s, warp, 0, g, tg, lane);
        conv3_tile<2>(smf, offk, b3s, 4, 2 * warp, g, tg, lane);
    }
    __syncthreads();

    {   // writeback
        const int s = tid >> 4, li = tid & 15;
        const int sg = s_off + blockIdx.x * 8 + s;
        if (sg < nsamp) {
            float* f = g_feats + (size_t)sg * FEAT_PAD;
            for (int i = li; i < 576; i += 16) {
                const int co = i / 9, p = i - 9 * co;
                const int r = s * 9 + p;
                f[i] = smf[(r / 18) * 4032 + 384 + (r % 18) * 65 + co];
            }
        }
    }
}

// ---------------------------------------------------------------------------
// Kernel 2: BM=64, double-buffered tf32 GEMM + tensor-core heads (round-12).
// ---------------------------------------------------------------------------
#define FC1_SMEM (12992 * 4)

__global__ __launch_bounds__(256) void k_fc1(
    const float* __restrict__ ptb1, const float* __restrict__ cfb1,
    const float* __restrict__ ptb2,
    const float* __restrict__ ptw3, const float* __restrict__ ptb3,
    const float* __restrict__ cfw2, const float* __restrict__ cfb2,
    float* __restrict__ out, int m_off)
{
    extern __shared__ float sfc[];
    unsigned* A_s = (unsigned*)sfc;            // 2 x 1024
    unsigned* B_s = (unsigned*)(sfc + 2048);   // 2 x 3072
    float* C1s    = sfc;                       // 12544 (post-GEMM alias)
    float* BiasS  = sfc + 12544;               // 192
    float* W3s    = sfc + 12736;               // 128
    float* CW2s   = sfc + 12864;               // 64
    float* B2s    = sfc + 12928;               // 64

    const int t = threadIdx.x;
    const int m0 = m_off + blockIdx.x * 64;
    const int warp = t >> 5, lane = t & 31;
    const int wm = warp >> 1, wn = warp & 1;
    const int g = lane >> 2, tg = lane & 3;

    if (t < 192) BiasS[t] = (t < 128) ? __ldg(ptb1 + t) : __ldg(cfb1 + t - 128);
    if (t < 128) W3s[t] = __ldg(ptw3 + t);
    if (t < 64)  { CW2s[t] = __ldg(cfw2 + t); B2s[t] = __ldg(ptb2 + t); }

    float acc[12][4];
    #pragma unroll
    for (int j = 0; j < 12; j++)
        #pragma unroll
        for (int r = 0; r < 4; r++) acc[j][r] = 0.f;

    const bool aload = (t < 128);
    const int am = t >> 1;
    const int kcA = t & 1;
    const int rA = am & 15, mtA = (am >> 4) & 3;
    const int baseA = ((kcA * 4 + mtA) * 32 + (rA & 7) * 4) * 4 + (rA >> 3);
    const float* arow = g_feats + (size_t)(m0 + (am & 63)) * FEAT_PAD + kcA * 8;

    float4 av0 = make_float4(0.f, 0.f, 0.f, 0.f);
    float4 av1 = av0;
    if (aload) { av0 = *(const float4*)(arow); av1 = *(const float4*)(arow + 4); }
    uint4 bv0 = *(const uint4*)(g_bfrag + t * 12);
    uint4 bv1 = *(const uint4*)(g_bfrag + t * 12 + 4);
    uint4 bv2 = *(const uint4*)(g_bfrag + t * 12 + 8);

    int p = 0;
    for (int it = 0; it < 37; ++it) {
        unsigned* Ab = A_s + p * 1024;
        unsigned* Bb = B_s + p * 3072;
        if (aload) {
            Ab[baseA + 0 * 4 + 0] = f2tf32(av0.x);
            Ab[baseA + 1 * 4 + 0] = f2tf32(av0.y);
            Ab[baseA + 2 * 4 + 0] = f2tf32(av0.z);
            Ab[baseA + 3 * 4 + 0] = f2tf32(av0.w);
            Ab[baseA + 0 * 4 + 2] = f2tf32(av1.x);
            Ab[baseA + 1 * 4 + 2] = f2tf32(av1.y);
            Ab[baseA + 2 * 4 + 2] = f2tf32(av1.z);
            Ab[baseA + 3 * 4 + 2] = f2tf32(av1.w);
        }
        *(uint4*)(Bb + t * 12)     = bv0;
        *(uint4*)(Bb + t * 12 + 4) = bv1;
        *(uint4*)(Bb + t * 12 + 8) = bv2;
        __syncthreads();
        if (it < 36) {
            if (aload) {
                av0 = *(const float4*)(arow + (it + 1) * 16);
                av1 = *(const float4*)(arow + (it + 1) * 16 + 4);
            }
            const unsigned* bsrc = g_bfrag + (it + 1) * 3072 + t * 12;
            bv0 = *(const uint4*)(bsrc);
            bv1 = *(const uint4*)(bsrc + 4);
            bv2 = *(const uint4*)(bsrc + 8);
        }
        #pragma unroll
        for (int kc = 0; kc < 2; kc++) {
            const uint4 v = *(const uint4*)(Ab + ((kc * 4 + wm) * 32 + lane) * 4);
            #pragma unroll
            for (int j = 0; j < 12; j++) {
                const uint2 b = *(const uint2*)(Bb + ((kc * 24 + wn * 12 + j) * 32 + lane) * 2);
                MMA_TF32(acc[j], v.x, v.y, v.z, v.w, b.x, b.y);
            }
        }
        p ^= 1;
    }
    __syncthreads();

    #pragma unroll
    for (int j = 0; j < 12; j++)
        #pragma unroll
        for (int r = 0; r < 4; r++) {
            const int m = wm * 16 + ((r >> 1) << 3) + g;
            const int n = wn * 96 + j * 8 + tg * 2 + (r & 1);
            C1s[m * 196 + n] = fmaxf(acc[j][r] + BiasS[n], 0.f);
        }
    __syncthreads();

    if (warp < 4) {
        const int base = warp * 16;
        float hacc[8][4];
        #pragma unroll
        for (int j = 0; j < 8; j++)
            #pragma unroll
            for (int r = 0; r < 4; r++) hacc[j][r] = 0.f;

        #pragma unroll 4
        for (int k8 = 0; k8 < 16; k8++) {
            const float* cA = C1s + base * 196 + k8 * 8;
            const unsigned a0 = f2tf32(cA[g * 196 + tg]);
            const unsigned a1 = f2tf32(cA[(g + 8) * 196 + tg]);
            const unsigned a2 = f2tf32(cA[g * 196 + tg + 4]);
            const unsigned a3 = f2tf32(cA[(g + 8) * 196 + tg + 4]);
            #pragma unroll
            for (int j = 0; j < 8; j++) {
                const uint2 b = __ldg((const uint2*)g_w2frag + (k8 * 8 + j) * 32 + lane);
                MMA_TF32(hacc[j], a0, a1, a2, a3, b.x, b.y);
            }
        }

        float l0g = 0.f, l1g = 0.f, l0h = 0.f, l1h = 0.f;
        #pragma unroll
        for (int j = 0; j < 8; j++)
            #pragma unroll
            for (int r = 0; r < 4; r++) {
                const int n = j * 8 + tg * 2 + (r & 1);
                const float v = fmaxf(hacc[j][r] + B2s[n], 0.f);
                const float w30 = W3s[n * 2], w31 = W3s[n * 2 + 1];
                if (r < 2) { l0g = fmaf(v, w30, l0g); l1g = fmaf(v, w31, l1g); }
                else       { l0h = fmaf(v, w30, l0h); l1h = fmaf(v, w31, l1h); }
            }
        #pragma unroll
        for (int off = 1; off <= 2; off <<= 1) {
            l0g += __shfl_xor_sync(0xffffffffu, l0g, off);
            l1g += __shfl_xor_sync(0xffffffffu, l1g, off);
            l0h += __shfl_xor_sync(0xffffffffu, l0h, off);
            l1h += __shfl_xor_sync(0xffffffffu, l1h, off);
        }
        if (tg == 0) {
            const float b30 = __ldg(ptb3 + 0), b31 = __ldg(ptb3 + 1);
            {
                const float l0 = l0g + b30, l1 = l1g + b31;
                const float mx = fmaxf(l0, l1);
                const float e0 = expf(l0 - mx), e1 = expf(l1 - mx);
                const float inv = 1.f / (e0 + e1);
                out[(size_t)(m0 + base + g) * 3 + 0] = e0 * inv;
                out[(size_t)(m0 + base + g) * 3 + 1] = e1 * inv;
            }
            {
                const float l0 = l0h + b30, l1 = l1h + b31;
                const float mx = fmaxf(l0, l1);
                const float e0 = expf(l0 - mx), e1 = expf(l1 - mx);
                const float inv = 1.f / (e0 + e1);
                out[(size_t)(m0 + base + g + 8) * 3 + 0] = e0 * inv;
                out[(size_t)(m0 + base + g + 8) * 3 + 1] = e1 * inv;
            }
        }
    } else {
        const int base = (warp - 4) * 16;
        for (int i = 0; i < 16; i++) {
            const int ml = base + i;
            const float* c1 = C1s + ml * 196;
            float cc = c1[128 + lane] * CW2s[lane] + c1[160 + lane] * CW2s[lane + 32];
            #pragma unroll
            for (int off = 16; off; off >>= 1)
                cc += __shfl_xor_sync(0xffffffffu, cc, off);
            if (lane == 0)
                out[(size_t)(m0 + ml) * 3 + 2] =
                    1.f / (1.f + expf(-(cc + __ldg(cfb2))));
        }
    }
}

// ---------------------------------------------------------------------------
// Launch: 4-chunk conv->fc1 pipeline (round-12 schedule) + split prep with
// the fc-weight bake overlapping conv on s2.
// ---------------------------------------------------------------------------
extern "C" void kernel_launch(void* const* d_in, const int* in_sizes, int n_in,
                              void* d_out, int out_size)
{
    const float* board = (const float*)d_in[0];
    // d_in[1] = target_positions (int64) — mathematically unused
    const float* c1w = (const float*)d_in[2];  const float* c1b = (const float*)d_in[3];
    const float* c2w = (const float*)d_in[4];  const float* c2b = (const float*)d_in[5];
    const float* c3w = (const float*)d_in[6];  const float* c3b = (const float*)d_in[7];
    const float* qp  = (const float*)d_in[8];
    const float* ptw1 = (const float*)d_in[9];  const float* ptb1 = (const float*)d_in[10];
    const float* ptw2 = (const float*)d_in[11]; const float* ptb2 = (const float*)d_in[12];
    const float* ptw3 = (const float*)d_in[13]; const float* ptb3 = (const float*)d_in[14];
    const float* cfw1 = (const float*)d_in[15]; const float* cfb1 = (const float*)d_in[16];
    const float* cfw2 = (const float*)d_in[17]; const float* cfb2 = (const float*)d_in[18];

    int B = in_sizes[0] / 108;
    if (B > BATCH_MAX) B = BATCH_MAX;

    static bool init_done = false;
    static cudaStream_t s2;
    static cudaEvent_t evc[4], evj;
    if (!init_done) {
        cudaFuncSetAttribute(k_conv, cudaFuncAttributeMaxDynamicSharedMemorySize, 4 * 2016 * 8);
        cudaFuncSetAttribute(k_fc1, cudaFuncAttributeMaxDynamicSharedMemorySize, FC1_SMEM);
        cudaStreamCreateWithFlags(&s2, cudaStreamNonBlocking);
        for (int i = 0; i < 4; i++)
            cudaEventCreateWithFlags(&evc[i], cudaEventDisableTiming);
        cudaEventCreateWithFlags(&evj, cudaEventDisableTiming);
        init_done = true;
    }

    // chunking: 4 chunks when cleanly divisible (conv: 8/blk, fc1: 64/blk)
    const int nch = (B % (512 * 4) == 0) ? 4 : 1;
    const int chunk = B / nch;

    // fc1 weight bake on s2 (overlaps conv chunks); conv bake on stream 0.
    k_prep_fc<<<(74 * 24 * 64 + 255) / 256, 256, 0, s2>>>(ptw1, cfw1, ptw2);
    k_prep_conv<<<72, 256>>>(c1w, c2w, c3w);

    for (int i = 0; i < nch; i++) {
        k_conv<<<(chunk + 7) / 8, 128, 4 * 2016 * 8>>>(
            board, c1b, c2b, c3b, qp, B, i * chunk);
        cudaEventRecord(evc[i], 0);
    }
    for (int i = 0; i < nch; i++) {
        cudaStreamWaitEvent(s2, evc[i], 0);
        k_fc1<<<chunk / 64, 256, FC1_SMEM, s2>>>(
            ptb1, cfb1, ptb2, ptw3, ptb3, cfw2, cfb2,
            (float*)d_out, i * chunk);
    }
    cudaEventRecord(evj, s2);
    cudaStreamWaitEvent(0, evj, 0);
}